// round 1
// baseline (speedup 1.0000x reference)
#include <cuda_runtime.h>
#include <cuda_bf16.h>
#include <math.h>

// ---------------- problem constants ----------------
#define BB      4
#define LL      4096
#define DMODEL  512
#define DINNER  1024
#define DSTATE  64
#define HEADD   64
#define NHEADS  16
#define CONVD   1152        // DINNER + 2*DSTATE
#define NPROJ   2192        // 2*DINNER + 2*DSTATE + NHEADS
#define BL      (BB*LL)     // 16384

// ---------------- scratch (device globals; no runtime alloc allowed) ----------------
__device__ float g_zx [(size_t)BL * NPROJ];   // in_proj output  [BL, 2192]
__device__ float g_xc [(size_t)BL * CONVD];   // conv+silu out   [BL, 1152]
__device__ float g_ys [(size_t)BL * DINNER];  // scan output     [BL, 1024]
__device__ float g_yb [(size_t)BL * DINNER];  // gated+rmsnorm   [BL, 1024]
__device__ float g_y2 [(size_t)BL * DMODEL];  // out_proj out    [BL, 512]
__device__ float g_yln[(size_t)BL * DMODEL];  // layernorm out   [BL, 512]
__device__ float g_h1 [(size_t)BL * DINNER];  // mlp hidden      [BL, 1024]
__device__ float g_w1e[1024 * 512];           // w1[:, :512] + w1[:, 512:]

// ---------------- generic SGEMM:  C[M,N] = A[M,K] @ W[N,K]^T  (+epilogue) ----------
// EPI: 0 = none, 1 = +bias, 2 = +bias then silu
template<int EPI>
__global__ void __launch_bounds__(256)
sgemm_kernel(const float* __restrict__ A, const float* __restrict__ W,
             const float* __restrict__ bias, float* __restrict__ C,
             int M, int N, int K)
{
    const int BM = 128, BN = 128, BK = 16;
    __shared__ float As[BK][BM];
    __shared__ float Bs[BK][BN];

    int n0 = blockIdx.x * BN;
    int m0 = blockIdx.y * BM;
    int tid = threadIdx.x;
    int tx = tid & 15;        // n direction
    int ty = tid >> 4;        // m direction

    int ar = tid >> 2;        // 0..63   (row within tile, +64 for second half)
    int ac = (tid & 3) * 4;   // 0,4,8,12 (k offset, float4)

    float acc[8][8];
#pragma unroll
    for (int i = 0; i < 8; i++)
#pragma unroll
        for (int j = 0; j < 8; j++) acc[i][j] = 0.f;

    float4 zero4 = make_float4(0.f, 0.f, 0.f, 0.f);

    auto loadA = [&](int k0, int half) -> float4 {
        int r = ar + half * 64;
        return *(const float4*)&A[(size_t)(m0 + r) * K + k0 + ac];
    };
    auto loadB = [&](int k0, int half) -> float4 {
        int r = ar + half * 64;
        int n = n0 + r;
        return (n < N) ? *(const float4*)&W[(size_t)n * K + k0 + ac] : zero4;
    };
    auto storeA = [&](float4 v, int half) {
        int r = ar + half * 64;
        As[ac + 0][r] = v.x; As[ac + 1][r] = v.y; As[ac + 2][r] = v.z; As[ac + 3][r] = v.w;
    };
    auto storeB = [&](float4 v, int half) {
        int r = ar + half * 64;
        Bs[ac + 0][r] = v.x; Bs[ac + 1][r] = v.y; Bs[ac + 2][r] = v.z; Bs[ac + 3][r] = v.w;
    };

    // prologue: tile 0
    float4 a0 = loadA(0, 0), a1 = loadA(0, 1);
    float4 b0 = loadB(0, 0), b1 = loadB(0, 1);
    storeA(a0, 0); storeA(a1, 1); storeB(b0, 0); storeB(b1, 1);
    __syncthreads();

    for (int k0 = 0; k0 < K; k0 += BK) {
        bool nxt = (k0 + BK) < K;
        if (nxt) {
            a0 = loadA(k0 + BK, 0); a1 = loadA(k0 + BK, 1);
            b0 = loadB(k0 + BK, 0); b1 = loadB(k0 + BK, 1);
        }
#pragma unroll
        for (int k = 0; k < BK; k++) {
            float a[8], b[8];
            *(float4*)&a[0] = *(const float4*)&As[k][ty * 8];
            *(float4*)&a[4] = *(const float4*)&As[k][ty * 8 + 4];
            *(float4*)&b[0] = *(const float4*)&Bs[k][tx * 8];
            *(float4*)&b[4] = *(const float4*)&Bs[k][tx * 8 + 4];
#pragma unroll
            for (int i = 0; i < 8; i++)
#pragma unroll
                for (int j = 0; j < 8; j++) acc[i][j] += a[i] * b[j];
        }
        if (nxt) {
            __syncthreads();
            storeA(a0, 0); storeA(a1, 1); storeB(b0, 0); storeB(b1, 1);
            __syncthreads();
        }
    }

#pragma unroll
    for (int i = 0; i < 8; i++) {
        int m = m0 + ty * 8 + i;
        size_t base = (size_t)m * N;
#pragma unroll
        for (int j = 0; j < 8; j++) {
            int n = n0 + tx * 8 + j;
            if (n < N) {
                float v = acc[i][j];
                if (EPI >= 1) v += bias[n];
                if (EPI == 2) v = v / (1.f + expf(-v));
                C[base + n] = v;
            }
        }
    }
}

// ---------------- conv (anti-causal in natural order) + silu ----------------
// out_nat[l, c] = silu( conv_b[c] + sum_k conv_w[c,k] * xBC_nat[l+3-k, c] ),  oob -> 0
__global__ void __launch_bounds__(256)
conv_silu_kernel(const float* __restrict__ zx, const float* __restrict__ cw,
                 const float* __restrict__ cb, float* __restrict__ xc)
{
    size_t idx = (size_t)blockIdx.x * blockDim.x + threadIdx.x;
    if (idx >= (size_t)BL * CONVD) return;
    int c  = (int)(idx % CONVD);
    int bl = (int)(idx / CONVD);
    int l  = bl % LL;

    float acc = cb[c];
    const float* base = zx + (size_t)bl * NPROJ + DINNER + c;
#pragma unroll
    for (int k = 0; k < 4; k++) {
        int off = 3 - k;
        if (l + off < LL) acc += cw[c * 4 + k] * base[(size_t)off * NPROJ];
    }
    acc = acc / (1.f + expf(-acc));  // silu
    xc[idx] = acc;
}

// ---------------- selective scan (backward in natural time) ----------------
// 128 blocks: (b, h, phalf). 256 threads: p_local(32) x ng(8); 8 states/thread.
__global__ void __launch_bounds__(256)
scan_kernel(const float* __restrict__ zx, const float* __restrict__ xc,
            const float* __restrict__ dt_bias, const float* __restrict__ A_log,
            float* __restrict__ yout)
{
    int blk   = blockIdx.x;
    int bh    = blk >> 1;
    int phalf = blk & 1;
    int b = bh >> 4, h = bh & 15;
    int tid = threadIdx.x;
    int pl = tid >> 3;            // 0..31
    int ng = tid & 7;             // 0..7
    int pg = phalf * 32 + pl;     // global p

    float Acoef = -expf(A_log[h]);
    float dtb   = dt_bias[h];

    __shared__ float sB[8][64], sC[8][64], sX[8][32];
    __shared__ float sdt[8], sDA[8];

    float hs[8];
#pragma unroll
    for (int j = 0; j < 8; j++) hs[j] = 0.f;

    for (int s0 = 0; s0 < LL; s0 += 8) {
        // load B and C (contiguous cols 1024..1151 of xc)
        for (int e = tid; e < 1024; e += 256) {
            int t = e >> 7, q = e & 127;
            int bl = b * LL + (LL - 1 - (s0 + t));
            float v = xc[(size_t)bl * CONVD + DINNER + q];
            if (q < 64) sB[t][q] = v; else sC[t][q - 64] = v;
        }
        // load xh slice for this block's 32 p values
        {
            int t = tid >> 5, j = tid & 31;
            int bl = b * LL + (LL - 1 - (s0 + t));
            sX[t][j] = xc[(size_t)bl * CONVD + h * HEADD + phalf * 32 + j];
        }
        // dt (softplus) and dA
        if (tid < 8) {
            int t = tid;
            int bl = b * LL + (LL - 1 - (s0 + t));
            float dr = zx[(size_t)bl * NPROJ + (2 * DINNER + 2 * DSTATE) + h] + dtb;
            float dt = (dr > 20.f) ? dr : log1pf(expf(dr));
            sdt[t] = dt;
            sDA[t] = expf(dt * Acoef);
        }
        __syncthreads();

#pragma unroll
        for (int t = 0; t < 8; t++) {
            float dA  = sDA[t];
            float dtx = sdt[t] * sX[t][pl];
            float4 bb0 = *(const float4*)&sB[t][ng * 8];
            float4 bb1 = *(const float4*)&sB[t][ng * 8 + 4];
            hs[0] = hs[0] * dA + dtx * bb0.x;
            hs[1] = hs[1] * dA + dtx * bb0.y;
            hs[2] = hs[2] * dA + dtx * bb0.z;
            hs[3] = hs[3] * dA + dtx * bb0.w;
            hs[4] = hs[4] * dA + dtx * bb1.x;
            hs[5] = hs[5] * dA + dtx * bb1.y;
            hs[6] = hs[6] * dA + dtx * bb1.z;
            hs[7] = hs[7] * dA + dtx * bb1.w;
            float4 cc0 = *(const float4*)&sC[t][ng * 8];
            float4 cc1 = *(const float4*)&sC[t][ng * 8 + 4];
            float yp = hs[0] * cc0.x + hs[1] * cc0.y + hs[2] * cc0.z + hs[3] * cc0.w
                     + hs[4] * cc1.x + hs[5] * cc1.y + hs[6] * cc1.z + hs[7] * cc1.w;
            yp += __shfl_xor_sync(0xffffffffu, yp, 1);
            yp += __shfl_xor_sync(0xffffffffu, yp, 2);
            yp += __shfl_xor_sync(0xffffffffu, yp, 4);
            if (ng == 0) {
                int l = LL - 1 - (s0 + t);
                yout[((size_t)(b * LL + l)) * DINNER + h * HEADD + pg] = yp;
            }
        }
        __syncthreads();
    }
}

// ---------------- block reduction helper ----------------
__device__ __forceinline__ float block_reduce_sum(float v) {
    __shared__ float sred[32];
    int lane = threadIdx.x & 31, w = threadIdx.x >> 5;
#pragma unroll
    for (int o = 16; o; o >>= 1) v += __shfl_xor_sync(0xffffffffu, v, o);
    if (lane == 0) sred[w] = v;
    __syncthreads();
    int nw = blockDim.x >> 5;
    float r = (threadIdx.x < nw) ? sred[threadIdx.x] : 0.f;
    if (w == 0) {
#pragma unroll
        for (int o = 16; o; o >>= 1) r += __shfl_xor_sync(0xffffffffu, r, o);
        if (lane == 0) sred[0] = r;
    }
    __syncthreads();
    float out = sred[0];
    __syncthreads();
    return out;
}

// ---------------- gate (y + D*xh) * silu(z), rmsnorm, * rms_w ----------------
__global__ void __launch_bounds__(256)
gate_rms_kernel(const float* __restrict__ ys, const float* __restrict__ xc,
                const float* __restrict__ zx, const float* __restrict__ Dv,
                const float* __restrict__ rw, float* __restrict__ yb)
{
    int row = blockIdx.x;
    size_t oy = (size_t)row * DINNER, oc = (size_t)row * CONVD, oz = (size_t)row * NPROJ;
    float v[4];
    float ss = 0.f;
#pragma unroll
    for (int i = 0; i < 4; i++) {
        int c = threadIdx.x + i * 256;
        float z = zx[oz + c];
        float sz = z / (1.f + expf(-z));
        float val = (ys[oy + c] + Dv[c >> 6] * xc[oc + c]) * sz;
        v[i] = val;
        ss += val * val;
    }
    ss = block_reduce_sum(ss);
    float r = rsqrtf(ss * (1.f / (float)DINNER) + 1e-5f);
#pragma unroll
    for (int i = 0; i < 4; i++) {
        int c = threadIdx.x + i * 256;
        yb[oy + c] = v[i] * r * rw[c];
    }
}

// ---------------- layernorm over 512 ----------------
__global__ void __launch_bounds__(128)
layernorm_kernel(const float* __restrict__ x, const float* __restrict__ g,
                 const float* __restrict__ bpar, float* __restrict__ out)
{
    int row = blockIdx.x;
    size_t o = (size_t)row * DMODEL;
    float v[4];
    float s = 0.f;
#pragma unroll
    for (int i = 0; i < 4; i++) {
        int c = threadIdx.x + i * 128;
        v[i] = x[o + c];
        s += v[i];
    }
    s = block_reduce_sum(s);
    float m = s * (1.f / (float)DMODEL);
    float ss = 0.f;
#pragma unroll
    for (int i = 0; i < 4; i++) { float d = v[i] - m; ss += d * d; }
    ss = block_reduce_sum(ss);
    float r = rsqrtf(ss * (1.f / (float)DMODEL) + 1e-5f);
#pragma unroll
    for (int i = 0; i < 4; i++) {
        int c = threadIdx.x + i * 128;
        out[o + c] = (v[i] - m) * r * g[c] + bpar[c];
    }
}

// ---------------- w1eff = w1[:, :512] + w1[:, 512:] ----------------
__global__ void __launch_bounds__(256)
w1eff_kernel(const float* __restrict__ w1, float* __restrict__ w1e)
{
    int idx = blockIdx.x * blockDim.x + threadIdx.x;
    if (idx >= 1024 * 512) return;
    int n = idx / 512, k = idx % 512;
    w1e[idx] = w1[n * 1024 + k] + w1[n * 1024 + 512 + k];
}

// ---------------- launch ----------------
extern "C" void kernel_launch(void* const* d_in, const int* in_sizes, int n_in,
                              void* d_out, int out_size)
{
    const float* x         = (const float*)d_in[0];
    const float* in_proj_w = (const float*)d_in[1];
    const float* conv_w    = (const float*)d_in[2];
    const float* conv_b    = (const float*)d_in[3];
    const float* dt_bias   = (const float*)d_in[4];
    const float* A_log     = (const float*)d_in[5];
    const float* Dv        = (const float*)d_in[6];
    const float* rms_w     = (const float*)d_in[7];
    const float* out_proj  = (const float*)d_in[8];
    const float* ln_g      = (const float*)d_in[9];
    const float* ln_b      = (const float*)d_in[10];
    const float* w1        = (const float*)d_in[11];
    const float* b1        = (const float*)d_in[12];
    const float* w2        = (const float*)d_in[13];
    const float* b2        = (const float*)d_in[14];
    float* outp            = (float*)d_out;

    float *p_zx, *p_xc, *p_ys, *p_yb, *p_y2, *p_yln, *p_h1, *p_w1e;
    cudaGetSymbolAddress((void**)&p_zx,  g_zx);
    cudaGetSymbolAddress((void**)&p_xc,  g_xc);
    cudaGetSymbolAddress((void**)&p_ys,  g_ys);
    cudaGetSymbolAddress((void**)&p_yb,  g_yb);
    cudaGetSymbolAddress((void**)&p_y2,  g_y2);
    cudaGetSymbolAddress((void**)&p_yln, g_yln);
    cudaGetSymbolAddress((void**)&p_h1,  g_h1);
    cudaGetSymbolAddress((void**)&p_w1e, g_w1e);

    // w1 folding (independent; run first)
    w1eff_kernel<<<(1024 * 512 + 255) / 256, 256>>>(w1, p_w1e);

    // 1) in_proj:  g_zx[BL, 2192] = x @ in_proj_w^T
    {
        dim3 grid((NPROJ + 127) / 128, BL / 128);
        sgemm_kernel<0><<<grid, 256>>>(x, in_proj_w, nullptr, p_zx, BL, NPROJ, DMODEL);
    }
    // 2) conv + silu -> g_xc[BL, 1152]
    {
        size_t tot = (size_t)BL * CONVD;
        conv_silu_kernel<<<(unsigned)((tot + 255) / 256), 256>>>(p_zx, conv_w, conv_b, p_xc);
    }
    // 3) selective scan (backward in natural time) -> g_ys[BL, 1024]
    scan_kernel<<<128, 256>>>(p_zx, p_xc, dt_bias, A_log, p_ys);

    // 4) gate + rmsnorm -> g_yb
    gate_rms_kernel<<<BL, 256>>>(p_ys, p_xc, p_zx, Dv, rms_w, p_yb);

    // 5) out_proj: g_y2[BL, 512] = g_yb @ out_proj^T
    {
        dim3 grid(DMODEL / 128, BL / 128);
        sgemm_kernel<0><<<grid, 256>>>(p_yb, out_proj, nullptr, p_y2, BL, DMODEL, DINNER);
    }
    // 6) layernorm -> g_yln
    layernorm_kernel<<<BL, 128>>>(p_y2, ln_g, ln_b, p_yln);

    // 7) mlp hidden: g_h1[BL, 1024] = silu(g_yln @ w1eff^T + b1)
    {
        dim3 grid(DINNER / 128, BL / 128);
        sgemm_kernel<2><<<grid, 256>>>(p_yln, p_w1e, b1, p_h1, BL, DINNER, DMODEL);
    }
    // 8) output: out[BL, 512] = g_h1 @ w2^T + b2
    {
        dim3 grid(DMODEL / 128, BL / 128);
        sgemm_kernel<1><<<grid, 256>>>(p_h1, w2, b2, outp, BL, DMODEL, DINNER);
    }
}

// round 2
// speedup vs baseline: 1.3957x; 1.3957x over previous
#include <cuda_runtime.h>
#include <cuda_bf16.h>
#include <math.h>

// ---------------- problem constants ----------------
#define BB      4
#define LL      4096
#define DMODEL  512
#define DINNER  1024
#define DSTATE  64
#define HEADD   64
#define NHEADS  16
#define CONVD   1152        // DINNER + 2*DSTATE
#define NPROJ   2192        // 2*DINNER + 2*DSTATE + NHEADS
#define BL      (BB*LL)     // 16384

// ---------------- scratch (device globals; no runtime alloc allowed) ----------------
__device__ float g_zx [(size_t)BL * NPROJ];   // in_proj output  [BL, 2192]
__device__ float g_xc [(size_t)BL * CONVD];   // conv+silu out   [BL, 1152]
__device__ float g_ys [(size_t)BL * DINNER];  // scan output     [BL, 1024]
__device__ float g_yb [(size_t)BL * DINNER];  // gated+rmsnorm   [BL, 1024]
__device__ float g_y2 [(size_t)BL * DMODEL];  // out_proj out    [BL, 512]
__device__ float g_yln[(size_t)BL * DMODEL];  // layernorm out   [BL, 512]
__device__ float g_h1 [(size_t)BL * DINNER];  // mlp hidden      [BL, 1024]
__device__ float g_w1e[1024 * 512];           // w1[:, :512] + w1[:, 512:]

// ================= tensor-core split-bf16 GEMM =================
// C[M,N] = A[M,K] @ W[N,K]^T using bf16 hi/lo decomposition:
//   A = Ah + Al, W = Bh + Bl;  C ≈ AhBh + AhBl + AlBh  (fp32 accum)
// Tiles: 128x128x32, 256 threads (8 warps: 2 in M x 4 in N, warp tile 64x32).
// Smem rows: 64 bf16 = 128B = 8 chunks of 16B: [hi c0..3 | lo c0..3],
// chunk index swizzled with cc ^ (row & 7) -> conflict-free ldmatrix.

__device__ __forceinline__ unsigned pack_bf16(__nv_bfloat16 a, __nv_bfloat16 b) {
    unsigned short ua = *(unsigned short*)&a;
    unsigned short ub = *(unsigned short*)&b;
    return (unsigned)ua | ((unsigned)ub << 16);
}

__device__ __forceinline__ void ldsm_x4(unsigned &r0, unsigned &r1,
                                        unsigned &r2, unsigned &r3, unsigned addr) {
    asm volatile("ldmatrix.sync.aligned.m8n8.x4.shared.b16 {%0,%1,%2,%3}, [%4];"
                 : "=r"(r0), "=r"(r1), "=r"(r2), "=r"(r3) : "r"(addr));
}

__device__ __forceinline__ void mma16816(float* c, const unsigned* a, const unsigned* b) {
    asm volatile(
        "mma.sync.aligned.m16n8k16.row.col.f32.bf16.bf16.f32 "
        "{%0,%1,%2,%3}, {%4,%5,%6,%7}, {%8,%9}, {%0,%1,%2,%3};"
        : "+f"(c[0]), "+f"(c[1]), "+f"(c[2]), "+f"(c[3])
        : "r"(a[0]), "r"(a[1]), "r"(a[2]), "r"(a[3]), "r"(b[0]), "r"(b[1]));
}

// EPI: 0 = none, 1 = +bias, 2 = +bias then silu
template<int EPI>
__global__ void __launch_bounds__(256)
hgemm3_kernel(const float* __restrict__ A, const float* __restrict__ W,
              const float* __restrict__ bias, float* __restrict__ C,
              int M, int N, int K)
{
    __shared__ __nv_bfloat16 sA[128][64];
    __shared__ __nv_bfloat16 sB[128][64];

    const int tid  = threadIdx.x;
    const int lane = tid & 31;
    const int wid  = tid >> 5;
    const int wm   = wid & 1;      // 0..1 -> 64-row slab
    const int wn   = wid >> 1;     // 0..3 -> 32-col slab
    const int m0   = blockIdx.y * 128;
    const int n0   = blockIdx.x * 128;

    // ---- loader lane mapping: 4 passes of (32 rows x 32 floats) ----
    const int lr   = tid >> 3;        // row base 0..31
    const int lk   = (tid & 7) * 4;   // float offset in row
    const int lc   = (tid & 7) >> 1;  // 16B chunk 0..3
    const int lsub = tid & 1;         // 8B half within chunk

    float4 pa[4], pb[4];
    const float4 z4 = make_float4(0.f, 0.f, 0.f, 0.f);

    unsigned sA_u32 = (unsigned)__cvta_generic_to_shared(&sA[0][0]);
    unsigned sB_u32 = (unsigned)__cvta_generic_to_shared(&sB[0][0]);

    // ---- ldmatrix lane-constant addressing ----
    // A: m-tile mi -> row = wm*64 + mi*16 + (lane&7) + ((lane>>3)&1)*8, kc = lane>>4
    unsigned aBase[4]; int aSw[4];
    const int kcA = lane >> 4;
#pragma unroll
    for (int mi = 0; mi < 4; mi++) {
        int r = wm * 64 + mi * 16 + (lane & 7) + ((lane >> 3) & 1) * 8;
        aBase[mi] = sA_u32 + (unsigned)(r * 128);
        aSw[mi] = r & 7;
    }
    // B: pair pj -> row = wn*32 + pj*16 + ((lane>>4)&1)*8 + (lane&7), kc = (lane>>3)&1
    unsigned bBase[2]; int bSw[2];
    const int kcB = (lane >> 3) & 1;
#pragma unroll
    for (int pj = 0; pj < 2; pj++) {
        int r = wn * 32 + pj * 16 + ((lane >> 4) & 1) * 8 + (lane & 7);
        bBase[pj] = sB_u32 + (unsigned)(r * 128);
        bSw[pj] = r & 7;
    }

    float acc[4][4][4];
#pragma unroll
    for (int i = 0; i < 4; i++)
#pragma unroll
        for (int j = 0; j < 4; j++)
#pragma unroll
            for (int q = 0; q < 4; q++) acc[i][j][q] = 0.f;

    auto ldg_tiles = [&](int k0) {
#pragma unroll
        for (int p = 0; p < 4; p++) {
            int m = lr + p * 32;
            pa[p] = *(const float4*)&A[(size_t)(m0 + m) * K + k0 + lk];
            int n = n0 + m;
            pb[p] = (n < N) ? *(const float4*)&W[(size_t)n * K + k0 + lk] : z4;
        }
    };

    auto sts_one = [&](__nv_bfloat16 (*tile)[64], int m, float4 v) {
        __nv_bfloat16 hx = __float2bfloat16(v.x);
        __nv_bfloat16 hy = __float2bfloat16(v.y);
        __nv_bfloat16 hz = __float2bfloat16(v.z);
        __nv_bfloat16 hw = __float2bfloat16(v.w);
        __nv_bfloat16 lx = __float2bfloat16(v.x - __bfloat162float(hx));
        __nv_bfloat16 ly = __float2bfloat16(v.y - __bfloat162float(hy));
        __nv_bfloat16 lz = __float2bfloat16(v.z - __bfloat162float(hz));
        __nv_bfloat16 lw = __float2bfloat16(v.w - __bfloat162float(hw));
        uint2 hi; hi.x = pack_bf16(hx, hy); hi.y = pack_bf16(hz, hw);
        uint2 lo; lo.x = pack_bf16(lx, ly); lo.y = pack_bf16(lz, lw);
        char* rowb = (char*)&tile[m][0];
        int msw = m & 7;
        *(uint2*)(rowb + ((lc ^ msw) * 16) + lsub * 8)        = hi;
        *(uint2*)(rowb + (((lc + 4) ^ msw) * 16) + lsub * 8)  = lo;
    };

    auto sts_tiles = [&]() {
#pragma unroll
        for (int p = 0; p < 4; p++) {
            int m = lr + p * 32;
            sts_one(sA, m, pa[p]);
            sts_one(sB, m, pb[p]);
        }
    };

    auto mma_all = [&](unsigned (*a)[4], unsigned (*b)[2]) {
#pragma unroll
        for (int mi = 0; mi < 4; mi++)
#pragma unroll
            for (int nj = 0; nj < 4; nj++)
                mma16816(acc[mi][nj], a[mi], b[nj]);
    };

    // prologue
    ldg_tiles(0);
    sts_tiles();
    __syncthreads();

    const int nk = K >> 5;
    for (int it = 0; it < nk; it++) {
        if (it + 1 < nk) ldg_tiles((it + 1) * 32);

#pragma unroll
        for (int ks = 0; ks < 2; ks++) {
            unsigned ah[4][4], bh[4][2], bt[4][2];
            // A hi
#pragma unroll
            for (int mi = 0; mi < 4; mi++)
                ldsm_x4(ah[mi][0], ah[mi][1], ah[mi][2], ah[mi][3],
                        aBase[mi] + (unsigned)((((ks * 2 + kcA)) ^ aSw[mi]) * 16));
            // B hi
#pragma unroll
            for (int pj = 0; pj < 2; pj++) {
                unsigned r0, r1, r2, r3;
                ldsm_x4(r0, r1, r2, r3,
                        bBase[pj] + (unsigned)((((ks * 2 + kcB)) ^ bSw[pj]) * 16));
                bh[pj * 2][0] = r0; bh[pj * 2][1] = r1;
                bh[pj * 2 + 1][0] = r2; bh[pj * 2 + 1][1] = r3;
            }
            mma_all(ah, bh);      // Ah * Bh
            // B lo
#pragma unroll
            for (int pj = 0; pj < 2; pj++) {
                unsigned r0, r1, r2, r3;
                ldsm_x4(r0, r1, r2, r3,
                        bBase[pj] + (unsigned)((((ks * 2 + kcB + 4)) ^ bSw[pj]) * 16));
                bt[pj * 2][0] = r0; bt[pj * 2][1] = r1;
                bt[pj * 2 + 1][0] = r2; bt[pj * 2 + 1][1] = r3;
            }
            mma_all(ah, bt);      // Ah * Bl
            // A lo (reuse ah regs)
#pragma unroll
            for (int mi = 0; mi < 4; mi++)
                ldsm_x4(ah[mi][0], ah[mi][1], ah[mi][2], ah[mi][3],
                        aBase[mi] + (unsigned)((((ks * 2 + kcA + 4)) ^ aSw[mi]) * 16));
            mma_all(ah, bh);      // Al * Bh
        }

        __syncthreads();
        if (it + 1 < nk) {
            sts_tiles();
            __syncthreads();
        }
    }

    // ---- epilogue ----
    const int row0 = m0 + wm * 64 + (lane >> 2);
    const int col0 = n0 + wn * 32 + (lane & 3) * 2;
#pragma unroll
    for (int mi = 0; mi < 4; mi++) {
#pragma unroll
        for (int nj = 0; nj < 4; nj++) {
            int col = col0 + nj * 8;
            if (col < N) {
                float b0 = 0.f, b1 = 0.f;
                if (EPI >= 1) { b0 = bias[col]; b1 = bias[col + 1]; }
                float v0 = acc[mi][nj][0] + b0;
                float v1 = acc[mi][nj][1] + b1;
                float v2 = acc[mi][nj][2] + b0;
                float v3 = acc[mi][nj][3] + b1;
                if (EPI == 2) {
                    v0 = v0 / (1.f + expf(-v0));
                    v1 = v1 / (1.f + expf(-v1));
                    v2 = v2 / (1.f + expf(-v2));
                    v3 = v3 / (1.f + expf(-v3));
                }
                int r = row0 + mi * 16;
                float2 p0; p0.x = v0; p0.y = v1;
                float2 p1; p1.x = v2; p1.y = v3;
                *(float2*)&C[(size_t)r * N + col] = p0;
                *(float2*)&C[(size_t)(r + 8) * N + col] = p1;
            }
        }
    }
}

// ---------------- conv (anti-causal in natural order) + silu ----------------
__global__ void __launch_bounds__(256)
conv_silu_kernel(const float* __restrict__ zx, const float* __restrict__ cw,
                 const float* __restrict__ cb, float* __restrict__ xc)
{
    size_t idx = (size_t)blockIdx.x * blockDim.x + threadIdx.x;
    if (idx >= (size_t)BL * CONVD) return;
    int c  = (int)(idx % CONVD);
    int bl = (int)(idx / CONVD);
    int l  = bl % LL;

    float acc = cb[c];
    const float* base = zx + (size_t)bl * NPROJ + DINNER + c;
#pragma unroll
    for (int k = 0; k < 4; k++) {
        int off = 3 - k;
        if (l + off < LL) acc += cw[c * 4 + k] * base[(size_t)off * NPROJ];
    }
    acc = acc / (1.f + expf(-acc));  // silu
    xc[idx] = acc;
}

// ---------------- selective scan (backward in natural time) ----------------
__global__ void __launch_bounds__(256)
scan_kernel(const float* __restrict__ zx, const float* __restrict__ xc,
            const float* __restrict__ dt_bias, const float* __restrict__ A_log,
            float* __restrict__ yout)
{
    int blk   = blockIdx.x;
    int bh    = blk >> 1;
    int phalf = blk & 1;
    int b = bh >> 4, h = bh & 15;
    int tid = threadIdx.x;
    int pl = tid >> 3;            // 0..31
    int ng = tid & 7;             // 0..7
    int pg = phalf * 32 + pl;     // global p

    float Acoef = -expf(A_log[h]);
    float dtb   = dt_bias[h];

    __shared__ float sB[8][64], sC[8][64], sX[8][32];
    __shared__ float sdt[8], sDA[8];

    float hs[8];
#pragma unroll
    for (int j = 0; j < 8; j++) hs[j] = 0.f;

    for (int s0 = 0; s0 < LL; s0 += 8) {
        for (int e = tid; e < 1024; e += 256) {
            int t = e >> 7, q = e & 127;
            int bl = b * LL + (LL - 1 - (s0 + t));
            float v = xc[(size_t)bl * CONVD + DINNER + q];
            if (q < 64) sB[t][q] = v; else sC[t][q - 64] = v;
        }
        {
            int t = tid >> 5, j = tid & 31;
            int bl = b * LL + (LL - 1 - (s0 + t));
            sX[t][j] = xc[(size_t)bl * CONVD + h * HEADD + phalf * 32 + j];
        }
        if (tid < 8) {
            int t = tid;
            int bl = b * LL + (LL - 1 - (s0 + t));
            float dr = zx[(size_t)bl * NPROJ + (2 * DINNER + 2 * DSTATE) + h] + dtb;
            float dt = (dr > 20.f) ? dr : log1pf(expf(dr));
            sdt[t] = dt;
            sDA[t] = expf(dt * Acoef);
        }
        __syncthreads();

#pragma unroll
        for (int t = 0; t < 8; t++) {
            float dA  = sDA[t];
            float dtx = sdt[t] * sX[t][pl];
            float4 bb0 = *(const float4*)&sB[t][ng * 8];
            float4 bb1 = *(const float4*)&sB[t][ng * 8 + 4];
            hs[0] = hs[0] * dA + dtx * bb0.x;
            hs[1] = hs[1] * dA + dtx * bb0.y;
            hs[2] = hs[2] * dA + dtx * bb0.z;
            hs[3] = hs[3] * dA + dtx * bb0.w;
            hs[4] = hs[4] * dA + dtx * bb1.x;
            hs[5] = hs[5] * dA + dtx * bb1.y;
            hs[6] = hs[6] * dA + dtx * bb1.z;
            hs[7] = hs[7] * dA + dtx * bb1.w;
            float4 cc0 = *(const float4*)&sC[t][ng * 8];
            float4 cc1 = *(const float4*)&sC[t][ng * 8 + 4];
            float yp = hs[0] * cc0.x + hs[1] * cc0.y + hs[2] * cc0.z + hs[3] * cc0.w
                     + hs[4] * cc1.x + hs[5] * cc1.y + hs[6] * cc1.z + hs[7] * cc1.w;
            yp += __shfl_xor_sync(0xffffffffu, yp, 1);
            yp += __shfl_xor_sync(0xffffffffu, yp, 2);
            yp += __shfl_xor_sync(0xffffffffu, yp, 4);
            if (ng == 0) {
                int l = LL - 1 - (s0 + t);
                yout[((size_t)(b * LL + l)) * DINNER + h * HEADD + pg] = yp;
            }
        }
        __syncthreads();
    }
}

// ---------------- block reduction helper ----------------
__device__ __forceinline__ float block_reduce_sum(float v) {
    __shared__ float sred[32];
    int lane = threadIdx.x & 31, w = threadIdx.x >> 5;
#pragma unroll
    for (int o = 16; o; o >>= 1) v += __shfl_xor_sync(0xffffffffu, v, o);
    if (lane == 0) sred[w] = v;
    __syncthreads();
    int nw = blockDim.x >> 5;
    float r = (threadIdx.x < nw) ? sred[threadIdx.x] : 0.f;
    if (w == 0) {
#pragma unroll
        for (int o = 16; o; o >>= 1) r += __shfl_xor_sync(0xffffffffu, r, o);
        if (lane == 0) sred[0] = r;
    }
    __syncthreads();
    float out = sred[0];
    __syncthreads();
    return out;
}

// ---------------- gate (y + D*xh) * silu(z), rmsnorm, * rms_w ----------------
__global__ void __launch_bounds__(256)
gate_rms_kernel(const float* __restrict__ ys, const float* __restrict__ xc,
                const float* __restrict__ zx, const float* __restrict__ Dv,
                const float* __restrict__ rw, float* __restrict__ yb)
{
    int row = blockIdx.x;
    size_t oy = (size_t)row * DINNER, oc = (size_t)row * CONVD, oz = (size_t)row * NPROJ;
    float v[4];
    float ss = 0.f;
#pragma unroll
    for (int i = 0; i < 4; i++) {
        int c = threadIdx.x + i * 256;
        float z = zx[oz + c];
        float sz = z / (1.f + expf(-z));
        float val = (ys[oy + c] + Dv[c >> 6] * xc[oc + c]) * sz;
        v[i] = val;
        ss += val * val;
    }
    ss = block_reduce_sum(ss);
    float r = rsqrtf(ss * (1.f / (float)DINNER) + 1e-5f);
#pragma unroll
    for (int i = 0; i < 4; i++) {
        int c = threadIdx.x + i * 256;
        yb[oy + c] = v[i] * r * rw[c];
    }
}

// ---------------- layernorm over 512 ----------------
__global__ void __launch_bounds__(128)
layernorm_kernel(const float* __restrict__ x, const float* __restrict__ g,
                 const float* __restrict__ bpar, float* __restrict__ out)
{
    int row = blockIdx.x;
    size_t o = (size_t)row * DMODEL;
    float v[4];
    float s = 0.f;
#pragma unroll
    for (int i = 0; i < 4; i++) {
        int c = threadIdx.x + i * 128;
        v[i] = x[o + c];
        s += v[i];
    }
    s = block_reduce_sum(s);
    float m = s * (1.f / (float)DMODEL);
    float ss = 0.f;
#pragma unroll
    for (int i = 0; i < 4; i++) { float d = v[i] - m; ss += d * d; }
    ss = block_reduce_sum(ss);
    float r = rsqrtf(ss * (1.f / (float)DMODEL) + 1e-5f);
#pragma unroll
    for (int i = 0; i < 4; i++) {
        int c = threadIdx.x + i * 128;
        out[o + c] = (v[i] - m) * r * g[c] + bpar[c];
    }
}

// ---------------- w1eff = w1[:, :512] + w1[:, 512:] ----------------
__global__ void __launch_bounds__(256)
w1eff_kernel(const float* __restrict__ w1, float* __restrict__ w1e)
{
    int idx = blockIdx.x * blockDim.x + threadIdx.x;
    if (idx >= 1024 * 512) return;
    int n = idx / 512, k = idx % 512;
    w1e[idx] = w1[n * 1024 + k] + w1[n * 1024 + 512 + k];
}

// ---------------- launch ----------------
extern "C" void kernel_launch(void* const* d_in, const int* in_sizes, int n_in,
                              void* d_out, int out_size)
{
    const float* x         = (const float*)d_in[0];
    const float* in_proj_w = (const float*)d_in[1];
    const float* conv_w    = (const float*)d_in[2];
    const float* conv_b    = (const float*)d_in[3];
    const float* dt_bias   = (const float*)d_in[4];
    const float* A_log     = (const float*)d_in[5];
    const float* Dv        = (const float*)d_in[6];
    const float* rms_w     = (const float*)d_in[7];
    const float* out_proj  = (const float*)d_in[8];
    const float* ln_g      = (const float*)d_in[9];
    const float* ln_b      = (const float*)d_in[10];
    const float* w1        = (const float*)d_in[11];
    const float* b1        = (const float*)d_in[12];
    const float* w2        = (const float*)d_in[13];
    const float* b2        = (const float*)d_in[14];
    float* outp            = (float*)d_out;

    float *p_zx, *p_xc, *p_ys, *p_yb, *p_y2, *p_yln, *p_h1, *p_w1e;
    cudaGetSymbolAddress((void**)&p_zx,  g_zx);
    cudaGetSymbolAddress((void**)&p_xc,  g_xc);
    cudaGetSymbolAddress((void**)&p_ys,  g_ys);
    cudaGetSymbolAddress((void**)&p_yb,  g_yb);
    cudaGetSymbolAddress((void**)&p_y2,  g_y2);
    cudaGetSymbolAddress((void**)&p_yln, g_yln);
    cudaGetSymbolAddress((void**)&p_h1,  g_h1);
    cudaGetSymbolAddress((void**)&p_w1e, g_w1e);

    // w1 folding (independent; run first)
    w1eff_kernel<<<(1024 * 512 + 255) / 256, 256>>>(w1, p_w1e);

    // 1) in_proj:  g_zx[BL, 2192] = x @ in_proj_w^T
    {
        dim3 grid((NPROJ + 127) / 128, BL / 128);
        hgemm3_kernel<0><<<grid, 256>>>(x, in_proj_w, nullptr, p_zx, BL, NPROJ, DMODEL);
    }
    // 2) conv + silu -> g_xc[BL, 1152]
    {
        size_t tot = (size_t)BL * CONVD;
        conv_silu_kernel<<<(unsigned)((tot + 255) / 256), 256>>>(p_zx, conv_w, conv_b, p_xc);
    }
    // 3) selective scan -> g_ys[BL, 1024]
    scan_kernel<<<128, 256>>>(p_zx, p_xc, dt_bias, A_log, p_ys);

    // 4) gate + rmsnorm -> g_yb
    gate_rms_kernel<<<BL, 256>>>(p_ys, p_xc, p_zx, Dv, rms_w, p_yb);

    // 5) out_proj: g_y2[BL, 512] = g_yb @ out_proj^T
    {
        dim3 grid(DMODEL / 128, BL / 128);
        hgemm3_kernel<0><<<grid, 256>>>(p_yb, out_proj, nullptr, p_y2, BL, DMODEL, DINNER);
    }
    // 6) layernorm -> g_yln
    layernorm_kernel<<<BL, 128>>>(p_y2, ln_g, ln_b, p_yln);

    // 7) mlp hidden: g_h1[BL, 1024] = silu(g_yln @ w1eff^T + b1)
    {
        dim3 grid(DINNER / 128, BL / 128);
        hgemm3_kernel<2><<<grid, 256>>>(p_yln, p_w1e, b1, p_h1, BL, DINNER, DMODEL);
    }
    // 8) output: out[BL, 512] = g_h1 @ w2^T + b2
    {
        dim3 grid(DMODEL / 128, BL / 128);
        hgemm3_kernel<1><<<grid, 256>>>(p_h1, w2, b2, outp, BL, DMODEL, DINNER);
    }
}

// round 4
// speedup vs baseline: 2.0298x; 1.4543x over previous
#include <cuda_runtime.h>
#include <cuda_bf16.h>
#include <math.h>
#include <stdint.h>

// ---------------- problem constants ----------------
#define BB      4
#define LL      4096
#define DMODEL  512
#define DINNER  1024
#define DSTATE  64
#define HEADD   64
#define NHEADS  16
#define CONVD   1152        // DINNER + 2*DSTATE
#define NPROJ   2192        // 2*DINNER + 2*DSTATE + NHEADS
#define BL      (BB*LL)     // 16384

// ---------------- scratch (device globals; no runtime alloc allowed) ----------------
__device__ float g_zx [(size_t)BL * NPROJ];
__device__ float g_xc [(size_t)BL * CONVD];
__device__ float g_ys [(size_t)BL * DINNER];
__device__ float g_yb [(size_t)BL * DINNER];
__device__ float g_y2 [(size_t)BL * DMODEL];
__device__ float g_yln[(size_t)BL * DMODEL];
__device__ float g_h1 [(size_t)BL * DINNER];
__device__ float g_w1e[1024 * 512];

// ================= tensor-core split-bf16 GEMM (mma.sync), double-buffered =========
// C[M,N] = A[M,K] @ W[N,K]^T :  A=Ah+Al, W=Bh+Bl;  C ≈ AhBh + AhBl + AlBh (fp32 acc)
// CTA tile 128x128x32, 256 threads (8 warps: 2 M x 4 N, warp tile 64x32).
// Smem (dynamic, 64KB): 2 buffers x (A tile 16KB + B tile 16KB).
// Tile row: 64 bf16 = 128B = 8 chunks of 16B [hi c0..3 | lo c4..7],
// chunk swizzled with c ^ (row & 7) -> conflict-free ldmatrix + stores.

__device__ __forceinline__ unsigned pack_bf16(__nv_bfloat16 a, __nv_bfloat16 b) {
    unsigned short ua = *(unsigned short*)&a;
    unsigned short ub = *(unsigned short*)&b;
    return (unsigned)ua | ((unsigned)ub << 16);
}

__device__ __forceinline__ void ldsm_x4(unsigned &r0, unsigned &r1,
                                        unsigned &r2, unsigned &r3, unsigned addr) {
    asm volatile("ldmatrix.sync.aligned.m8n8.x4.shared.b16 {%0,%1,%2,%3}, [%4];"
                 : "=r"(r0), "=r"(r1), "=r"(r2), "=r"(r3) : "r"(addr));
}

__device__ __forceinline__ void mma16816(float* c, const unsigned* a, const unsigned* b) {
    asm volatile(
        "mma.sync.aligned.m16n8k16.row.col.f32.bf16.bf16.f32 "
        "{%0,%1,%2,%3}, {%4,%5,%6,%7}, {%8,%9}, {%0,%1,%2,%3};"
        : "+f"(c[0]), "+f"(c[1]), "+f"(c[2]), "+f"(c[3])
        : "r"(a[0]), "r"(a[1]), "r"(a[2]), "r"(a[3]), "r"(b[0]), "r"(b[1]));
}

#define TILE_BYTES   16384            // 128 rows x 128B
#define BUF_BYTES    (2 * TILE_BYTES) // A + B
#define GSM_BYTES    (2 * BUF_BYTES)  // double buffer = 64KB

// EPI: 0 = none, 1 = +bias, 2 = +bias then silu
template<int EPI>
__global__ void __launch_bounds__(256)
hgemm3_kernel(const float* __restrict__ A, const float* __restrict__ W,
              const float* __restrict__ bias, float* __restrict__ C,
              int M, int N, int K)
{
    extern __shared__ char smem[];

    const int tid  = threadIdx.x;
    const int lane = tid & 31;
    const int wid  = tid >> 5;
    const int wm   = wid & 1;      // 0..1 -> 64-row slab
    const int wn   = wid >> 1;     // 0..3 -> 32-col slab
    const int m0   = blockIdx.y * 128;
    const int n0   = blockIdx.x * 128;

    // ---- loader lane mapping: 4 passes of (32 rows x 32 floats) ----
    const int lr   = tid >> 3;        // row base 0..31
    const int lk   = (tid & 7) * 4;   // float offset in row
    const int lc   = (tid & 7) >> 1;  // 16B chunk 0..3
    const int lsub = tid & 1;         // 8B half within chunk

    float4 pa[4], pb[4];
    const float4 z4 = make_float4(0.f, 0.f, 0.f, 0.f);

    const unsigned s_u32 = (unsigned)__cvta_generic_to_shared(&smem[0]);

    // ---- ldmatrix lane-constant addressing (relative to buffer base) ----
    unsigned aBase[4]; int aSw[4];
    const int kcA = lane >> 4;
#pragma unroll
    for (int mi = 0; mi < 4; mi++) {
        int r = wm * 64 + mi * 16 + (lane & 7) + ((lane >> 3) & 1) * 8;
        aBase[mi] = s_u32 + (unsigned)(r * 128);
        aSw[mi] = r & 7;
    }
    unsigned bBase[2]; int bSw[2];
    const int kcB = (lane >> 3) & 1;
#pragma unroll
    for (int pj = 0; pj < 2; pj++) {
        int r = wn * 32 + pj * 16 + ((lane >> 4) & 1) * 8 + (lane & 7);
        bBase[pj] = s_u32 + (unsigned)(TILE_BYTES + r * 128);
        bSw[pj] = r & 7;
    }

    float acc[4][4][4];
#pragma unroll
    for (int i = 0; i < 4; i++)
#pragma unroll
        for (int j = 0; j < 4; j++)
#pragma unroll
            for (int q = 0; q < 4; q++) acc[i][j][q] = 0.f;

    auto ldg_tiles = [&](int k0) {
#pragma unroll
        for (int p = 0; p < 4; p++) {
            int m = lr + p * 32;
            pa[p] = *(const float4*)&A[(size_t)(m0 + m) * K + k0 + lk];
            int n = n0 + m;
            pb[p] = (n < N) ? *(const float4*)&W[(size_t)n * K + k0 + lk] : z4;
        }
    };

    auto sts_one = [&](int tileoff, int m, float4 v) {
        __nv_bfloat16 hx = __float2bfloat16(v.x);
        __nv_bfloat16 hy = __float2bfloat16(v.y);
        __nv_bfloat16 hz = __float2bfloat16(v.z);
        __nv_bfloat16 hw = __float2bfloat16(v.w);
        __nv_bfloat16 lx = __float2bfloat16(v.x - __bfloat162float(hx));
        __nv_bfloat16 ly = __float2bfloat16(v.y - __bfloat162float(hy));
        __nv_bfloat16 lz = __float2bfloat16(v.z - __bfloat162float(hz));
        __nv_bfloat16 lw = __float2bfloat16(v.w - __bfloat162float(hw));
        uint2 hi; hi.x = pack_bf16(hx, hy); hi.y = pack_bf16(hz, hw);
        uint2 lo; lo.x = pack_bf16(lx, ly); lo.y = pack_bf16(lz, lw);
        char* rowb = smem + tileoff + m * 128;
        int msw = m & 7;
        *(uint2*)(rowb + ((lc ^ msw) * 16) + lsub * 8)        = hi;
        *(uint2*)(rowb + (((lc + 4) ^ msw) * 16) + lsub * 8)  = lo;
    };

    auto sts_tiles = [&](int buf) {
        int boff = buf * BUF_BYTES;
#pragma unroll
        for (int p = 0; p < 4; p++) {
            int m = lr + p * 32;
            sts_one(boff, m, pa[p]);
            sts_one(boff + TILE_BYTES, m, pb[p]);
        }
    };

    auto mma_all = [&](unsigned (*a)[4], unsigned (*b)[2]) {
#pragma unroll
        for (int mi = 0; mi < 4; mi++)
#pragma unroll
            for (int nj = 0; nj < 4; nj++)
                mma16816(acc[mi][nj], a[mi], b[nj]);
    };

    // prologue
    ldg_tiles(0);
    sts_tiles(0);
    __syncthreads();

    const int nk = K >> 5;
    for (int it = 0; it < nk; it++) {
        const bool more = (it + 1) < nk;
        if (more) ldg_tiles((it + 1) * 32);

        const unsigned boff = (unsigned)((it & 1) * BUF_BYTES);
#pragma unroll
        for (int ks = 0; ks < 2; ks++) {
            unsigned ah[4][4], bh[4][2], bt[4][2];
            // A hi
#pragma unroll
            for (int mi = 0; mi < 4; mi++)
                ldsm_x4(ah[mi][0], ah[mi][1], ah[mi][2], ah[mi][3],
                        aBase[mi] + boff + (unsigned)((((ks * 2 + kcA)) ^ aSw[mi]) * 16));
            // B hi
#pragma unroll
            for (int pj = 0; pj < 2; pj++) {
                unsigned r0, r1, r2, r3;
                ldsm_x4(r0, r1, r2, r3,
                        bBase[pj] + boff + (unsigned)((((ks * 2 + kcB)) ^ bSw[pj]) * 16));
                bh[pj * 2][0] = r0; bh[pj * 2][1] = r1;
                bh[pj * 2 + 1][0] = r2; bh[pj * 2 + 1][1] = r3;
            }
            mma_all(ah, bh);      // Ah * Bh
            // B lo
#pragma unroll
            for (int pj = 0; pj < 2; pj++) {
                unsigned r0, r1, r2, r3;
                ldsm_x4(r0, r1, r2, r3,
                        bBase[pj] + boff + (unsigned)((((ks * 2 + kcB + 4)) ^ bSw[pj]) * 16));
                bt[pj * 2][0] = r0; bt[pj * 2][1] = r1;
                bt[pj * 2 + 1][0] = r2; bt[pj * 2 + 1][1] = r3;
            }
            mma_all(ah, bt);      // Ah * Bl
            // A lo (reuse ah regs)
#pragma unroll
            for (int mi = 0; mi < 4; mi++)
                ldsm_x4(ah[mi][0], ah[mi][1], ah[mi][2], ah[mi][3],
                        aBase[mi] + boff + (unsigned)((((ks * 2 + kcA + 4)) ^ aSw[mi]) * 16));
            mma_all(ah, bh);      // Al * Bh
        }

        if (more) sts_tiles((it + 1) & 1);
        __syncthreads();
    }

    // ---- epilogue ----
    const int row0 = m0 + wm * 64 + (lane >> 2);
    const int col0 = n0 + wn * 32 + (lane & 3) * 2;
#pragma unroll
    for (int mi = 0; mi < 4; mi++) {
#pragma unroll
        for (int nj = 0; nj < 4; nj++) {
            int col = col0 + nj * 8;
            if (col < N) {
                float b0 = 0.f, b1 = 0.f;
                if (EPI >= 1) { b0 = bias[col]; b1 = bias[col + 1]; }
                float v0 = acc[mi][nj][0] + b0;
                float v1 = acc[mi][nj][1] + b1;
                float v2 = acc[mi][nj][2] + b0;
                float v3 = acc[mi][nj][3] + b1;
                if (EPI == 2) {
                    v0 = v0 / (1.f + expf(-v0));
                    v1 = v1 / (1.f + expf(-v1));
                    v2 = v2 / (1.f + expf(-v2));
                    v3 = v3 / (1.f + expf(-v3));
                }
                int r = row0 + mi * 16;
                float2 p0; p0.x = v0; p0.y = v1;
                float2 p1; p1.x = v2; p1.y = v3;
                *(float2*)&C[(size_t)r * N + col] = p0;
                *(float2*)&C[(size_t)(r + 8) * N + col] = p1;
            }
        }
    }
}

// ---------------- conv (anti-causal in natural order) + silu ----------------
__global__ void __launch_bounds__(256)
conv_silu_kernel(const float* __restrict__ zx, const float* __restrict__ cw,
                 const float* __restrict__ cb, float* __restrict__ xc)
{
    size_t idx = (size_t)blockIdx.x * blockDim.x + threadIdx.x;
    if (idx >= (size_t)BL * CONVD) return;
    int c  = (int)(idx % CONVD);
    int bl = (int)(idx / CONVD);
    int l  = bl % LL;

    float acc = cb[c];
    const float* base = zx + (size_t)bl * NPROJ + DINNER + c;
#pragma unroll
    for (int k = 0; k < 4; k++) {
        int off = 3 - k;
        if (l + off < LL) acc += cw[c * 4 + k] * base[(size_t)off * NPROJ];
    }
    acc = acc / (1.f + expf(-acc));
    xc[idx] = acc;
}

// ---------------- selective scan (backward in natural time, double-buffered) --------
__global__ void __launch_bounds__(256)
scan_kernel(const float* __restrict__ zx, const float* __restrict__ xc,
            const float* __restrict__ dt_bias, const float* __restrict__ A_log,
            float* __restrict__ yout)
{
    int blk   = blockIdx.x;
    int bh    = blk >> 1;
    int phalf = blk & 1;
    int b = bh >> 4, h = bh & 15;
    int tid = threadIdx.x;
    int pl = tid >> 3;
    int ng = tid & 7;
    int pg = phalf * 32 + pl;

    float Acoef = -expf(A_log[h]);
    float dtb   = dt_bias[h];

    __shared__ float sB[2][8][64], sC[2][8][64], sX[2][8][32];
    __shared__ float sdt[2][8], sDA[2][8];

    float hs[8];
#pragma unroll
    for (int j = 0; j < 8; j++) hs[j] = 0.f;

    float rBC[4], rX, rDR = 0.f;
    const int xt = tid >> 5, xj = tid & 31;

    auto preload = [&](int s0) {
#pragma unroll
        for (int i = 0; i < 4; i++) {
            int e = tid + i * 256;
            int t = e >> 7, q = e & 127;
            int bl = b * LL + (LL - 1 - (s0 + t));
            rBC[i] = xc[(size_t)bl * CONVD + DINNER + q];
        }
        {
            int bl = b * LL + (LL - 1 - (s0 + xt));
            rX = xc[(size_t)bl * CONVD + h * HEADD + phalf * 32 + xj];
        }
        if (tid < 8) {
            int bl = b * LL + (LL - 1 - (s0 + tid));
            rDR = zx[(size_t)bl * NPROJ + (2 * DINNER + 2 * DSTATE) + h];
        }
    };
    auto commit_smem = [&](int buf) {
#pragma unroll
        for (int i = 0; i < 4; i++) {
            int e = tid + i * 256;
            int t = e >> 7, q = e & 127;
            if (q < 64) sB[buf][t][q] = rBC[i]; else sC[buf][t][q - 64] = rBC[i];
        }
        sX[buf][xt][xj] = rX;
        if (tid < 8) {
            float dr = rDR + dtb;
            float dt = (dr > 20.f) ? dr : log1pf(expf(dr));
            sdt[buf][tid] = dt;
            sDA[buf][tid] = expf(dt * Acoef);
        }
    };

    preload(0);
    commit_smem(0);
    __syncthreads();

    for (int s0 = 0; s0 < LL; s0 += 8) {
        int buf = (s0 >> 3) & 1;
        bool more = (s0 + 8) < LL;
        if (more) preload(s0 + 8);

#pragma unroll
        for (int t = 0; t < 8; t++) {
            float dA  = sDA[buf][t];
            float dtx = sdt[buf][t] * sX[buf][t][pl];
            float4 bb0 = *(const float4*)&sB[buf][t][ng * 8];
            float4 bb1 = *(const float4*)&sB[buf][t][ng * 8 + 4];
            hs[0] = hs[0] * dA + dtx * bb0.x;
            hs[1] = hs[1] * dA + dtx * bb0.y;
            hs[2] = hs[2] * dA + dtx * bb0.z;
            hs[3] = hs[3] * dA + dtx * bb0.w;
            hs[4] = hs[4] * dA + dtx * bb1.x;
            hs[5] = hs[5] * dA + dtx * bb1.y;
            hs[6] = hs[6] * dA + dtx * bb1.z;
            hs[7] = hs[7] * dA + dtx * bb1.w;
            float4 cc0 = *(const float4*)&sC[buf][t][ng * 8];
            float4 cc1 = *(const float4*)&sC[buf][t][ng * 8 + 4];
            float yp = hs[0] * cc0.x + hs[1] * cc0.y + hs[2] * cc0.z + hs[3] * cc0.w
                     + hs[4] * cc1.x + hs[5] * cc1.y + hs[6] * cc1.z + hs[7] * cc1.w;
            yp += __shfl_xor_sync(0xffffffffu, yp, 1);
            yp += __shfl_xor_sync(0xffffffffu, yp, 2);
            yp += __shfl_xor_sync(0xffffffffu, yp, 4);
            if (ng == 0) {
                int l = LL - 1 - (s0 + t);
                yout[((size_t)(b * LL + l)) * DINNER + h * HEADD + pg] = yp;
            }
        }
        if (more) commit_smem(buf ^ 1);
        __syncthreads();
    }
}

// ---------------- block reduction helper ----------------
__device__ __forceinline__ float block_reduce_sum(float v) {
    __shared__ float sred[32];
    int lane = threadIdx.x & 31, w = threadIdx.x >> 5;
#pragma unroll
    for (int o = 16; o; o >>= 1) v += __shfl_xor_sync(0xffffffffu, v, o);
    if (lane == 0) sred[w] = v;
    __syncthreads();
    int nw = blockDim.x >> 5;
    float r = (threadIdx.x < nw) ? sred[threadIdx.x] : 0.f;
    if (w == 0) {
#pragma unroll
        for (int o = 16; o; o >>= 1) r += __shfl_xor_sync(0xffffffffu, r, o);
        if (lane == 0) sred[0] = r;
    }
    __syncthreads();
    float out = sred[0];
    __syncthreads();
    return out;
}

// ---------------- gate (y + D*xh) * silu(z), rmsnorm, * rms_w ----------------
__global__ void __launch_bounds__(256)
gate_rms_kernel(const float* __restrict__ ys, const float* __restrict__ xc,
                const float* __restrict__ zx, const float* __restrict__ Dv,
                const float* __restrict__ rw, float* __restrict__ yb)
{
    int row = blockIdx.x;
    size_t oy = (size_t)row * DINNER, oc = (size_t)row * CONVD, oz = (size_t)row * NPROJ;
    float v[4];
    float ss = 0.f;
#pragma unroll
    for (int i = 0; i < 4; i++) {
        int c = threadIdx.x + i * 256;
        float z = zx[oz + c];
        float sz = z / (1.f + expf(-z));
        float val = (ys[oy + c] + Dv[c >> 6] * xc[oc + c]) * sz;
        v[i] = val;
        ss += val * val;
    }
    ss = block_reduce_sum(ss);
    float r = rsqrtf(ss * (1.f / (float)DINNER) + 1e-5f);
#pragma unroll
    for (int i = 0; i < 4; i++) {
        int c = threadIdx.x + i * 256;
        yb[oy + c] = v[i] * r * rw[c];
    }
}

// ---------------- layernorm over 512 ----------------
__global__ void __launch_bounds__(128)
layernorm_kernel(const float* __restrict__ x, const float* __restrict__ g,
                 const float* __restrict__ bpar, float* __restrict__ out)
{
    int row = blockIdx.x;
    size_t o = (size_t)row * DMODEL;
    float v[4];
    float s = 0.f;
#pragma unroll
    for (int i = 0; i < 4; i++) {
        int c = threadIdx.x + i * 128;
        v[i] = x[o + c];
        s += v[i];
    }
    s = block_reduce_sum(s);
    float m = s * (1.f / (float)DMODEL);
    float ss = 0.f;
#pragma unroll
    for (int i = 0; i < 4; i++) { float d = v[i] - m; ss += d * d; }
    ss = block_reduce_sum(ss);
    float r = rsqrtf(ss * (1.f / (float)DMODEL) + 1e-5f);
#pragma unroll
    for (int i = 0; i < 4; i++) {
        int c = threadIdx.x + i * 128;
        out[o + c] = (v[i] - m) * r * g[c] + bpar[c];
    }
}

// ---------------- w1eff = w1[:, :512] + w1[:, 512:] ----------------
__global__ void __launch_bounds__(256)
w1eff_kernel(const float* __restrict__ w1, float* __restrict__ w1e)
{
    int idx = blockIdx.x * blockDim.x + threadIdx.x;
    if (idx >= 1024 * 512) return;
    int n = idx / 512, k = idx % 512;
    w1e[idx] = w1[n * 1024 + k] + w1[n * 1024 + 512 + k];
}

// ---------------- launch ----------------
extern "C" void kernel_launch(void* const* d_in, const int* in_sizes, int n_in,
                              void* d_out, int out_size)
{
    const float* x         = (const float*)d_in[0];
    const float* in_proj_w = (const float*)d_in[1];
    const float* conv_w    = (const float*)d_in[2];
    const float* conv_b    = (const float*)d_in[3];
    const float* dt_bias   = (const float*)d_in[4];
    const float* A_log     = (const float*)d_in[5];
    const float* Dv        = (const float*)d_in[6];
    const float* rms_w     = (const float*)d_in[7];
    const float* out_proj  = (const float*)d_in[8];
    const float* ln_g      = (const float*)d_in[9];
    const float* ln_b      = (const float*)d_in[10];
    const float* w1        = (const float*)d_in[11];
    const float* b1        = (const float*)d_in[12];
    const float* w2        = (const float*)d_in[13];
    const float* b2        = (const float*)d_in[14];
    float* outp            = (float*)d_out;

    float *p_zx, *p_xc, *p_ys, *p_yb, *p_y2, *p_yln, *p_h1, *p_w1e;
    cudaGetSymbolAddress((void**)&p_zx,  g_zx);
    cudaGetSymbolAddress((void**)&p_xc,  g_xc);
    cudaGetSymbolAddress((void**)&p_ys,  g_ys);
    cudaGetSymbolAddress((void**)&p_yb,  g_yb);
    cudaGetSymbolAddress((void**)&p_y2,  g_y2);
    cudaGetSymbolAddress((void**)&p_yln, g_yln);
    cudaGetSymbolAddress((void**)&p_h1,  g_h1);
    cudaGetSymbolAddress((void**)&p_w1e, g_w1e);

    static bool attr_done = false;
    if (!attr_done) {
        cudaFuncSetAttribute(hgemm3_kernel<0>, cudaFuncAttributeMaxDynamicSharedMemorySize, GSM_BYTES);
        cudaFuncSetAttribute(hgemm3_kernel<1>, cudaFuncAttributeMaxDynamicSharedMemorySize, GSM_BYTES);
        cudaFuncSetAttribute(hgemm3_kernel<2>, cudaFuncAttributeMaxDynamicSharedMemorySize, GSM_BYTES);
        attr_done = true;
    }

    w1eff_kernel<<<(1024 * 512 + 255) / 256, 256>>>(w1, p_w1e);

    // 1) in_proj:  g_zx[BL, 2192] = x @ in_proj_w^T
    {
        dim3 grid((NPROJ + 127) / 128, BL / 128);
        hgemm3_kernel<0><<<grid, 256, GSM_BYTES>>>(x, in_proj_w, nullptr, p_zx, BL, NPROJ, DMODEL);
    }
    // 2) conv + silu
    {
        size_t tot = (size_t)BL * CONVD;
        conv_silu_kernel<<<(unsigned)((tot + 255) / 256), 256>>>(p_zx, conv_w, conv_b, p_xc);
    }
    // 3) selective scan
    scan_kernel<<<128, 256>>>(p_zx, p_xc, dt_bias, A_log, p_ys);
    // 4) gate + rmsnorm
    gate_rms_kernel<<<BL, 256>>>(p_ys, p_xc, p_zx, Dv, rms_w, p_yb);
    // 5) out_proj
    {
        dim3 grid(DMODEL / 128, BL / 128);
        hgemm3_kernel<0><<<grid, 256, GSM_BYTES>>>(p_yb, out_proj, nullptr, p_y2, BL, DMODEL, DINNER);
    }
    // 6) layernorm
    layernorm_kernel<<<BL, 128>>>(p_y2, ln_g, ln_b, p_yln);
    // 7) mlp hidden
    {
        dim3 grid(DINNER / 128, BL / 128);
        hgemm3_kernel<2><<<grid, 256, GSM_BYTES>>>(p_yln, p_w1e, b1, p_h1, BL, DINNER, DMODEL);
    }
    // 8) output
    {
        dim3 grid(DMODEL / 128, BL / 128);
        hgemm3_kernel<1><<<grid, 256, GSM_BYTES>>>(p_h1, w2, b2, outp, BL, DMODEL, DINNER);
    }
}

// round 5
// speedup vs baseline: 2.2545x; 1.1107x over previous
#include <cuda_runtime.h>
#include <cuda_bf16.h>
#include <math.h>
#include <stdint.h>

// ---------------- problem constants ----------------
#define BB      4
#define LL      4096
#define DMODEL  512
#define DINNER  1024
#define DSTATE  64
#define HEADD   64
#define NHEADS  16
#define CONVD   1152        // DINNER + 2*DSTATE
#define NPROJ   2192        // 2*DINNER + 2*DSTATE + NHEADS
#define BL      (BB*LL)     // 16384

// scan segmentation
#define SSEG    8
#define SEGL    (LL / SSEG)   // 512

// ---------------- scratch (device globals; no runtime alloc allowed) ----------------
__device__ float g_zx [(size_t)BL * NPROJ];
__device__ float g_xc [(size_t)BL * CONVD];
__device__ float g_ys [(size_t)BL * DINNER];
__device__ float g_yb [(size_t)BL * DINNER];
__device__ float g_y2 [(size_t)BL * DMODEL];
__device__ float g_yln[(size_t)BL * DMODEL];
__device__ float g_h1 [(size_t)BL * DINNER];
__device__ float g_w1e[1024 * 512];
__device__ float g_hseg[64 * 2 * SSEG * 2048];  // per (b,h,phalf,seg): 32p x 64n end-state
__device__ float g_hst [64 * 2 * SSEG * 2048];  // per-segment start states
__device__ float g_cum [64 * LL];               // per (b,h,s): cumulative prod dA within segment

// ================= tensor-core split-bf16 GEMM (mma.sync) =================
// C[M,N] = A[M,K] @ W[N,K]^T :  A=Ah+Al, W=Bh+Bl;  C ≈ AhBh + AhBl + AlBh (fp32 acc)
// CTA tile 128x128x32, 256 threads (8 warps: 2 M x 4 N, warp tile 64x32).
// Double-buffered smem, register-lean schedule targeting 2 CTAs/SM.

__device__ __forceinline__ unsigned pack_bf16(__nv_bfloat16 a, __nv_bfloat16 b) {
    unsigned short ua = *(unsigned short*)&a;
    unsigned short ub = *(unsigned short*)&b;
    return (unsigned)ua | ((unsigned)ub << 16);
}

__device__ __forceinline__ void ldsm_x4(unsigned &r0, unsigned &r1,
                                        unsigned &r2, unsigned &r3, unsigned addr) {
    asm volatile("ldmatrix.sync.aligned.m8n8.x4.shared.b16 {%0,%1,%2,%3}, [%4];"
                 : "=r"(r0), "=r"(r1), "=r"(r2), "=r"(r3) : "r"(addr));
}

__device__ __forceinline__ void mma16816(float* c, const unsigned* a, const unsigned* b) {
    asm volatile(
        "mma.sync.aligned.m16n8k16.row.col.f32.bf16.bf16.f32 "
        "{%0,%1,%2,%3}, {%4,%5,%6,%7}, {%8,%9}, {%0,%1,%2,%3};"
        : "+f"(c[0]), "+f"(c[1]), "+f"(c[2]), "+f"(c[3])
        : "r"(a[0]), "r"(a[1]), "r"(a[2]), "r"(a[3]), "r"(b[0]), "r"(b[1]));
}

#define TILE_BYTES   16384            // 128 rows x 128B
#define BUF_BYTES    (2 * TILE_BYTES) // A + B
#define GSM_BYTES    (2 * BUF_BYTES)  // double buffer = 64KB

// EPI: 0 = none, 1 = +bias, 2 = +bias then silu
template<int EPI>
__global__ void __launch_bounds__(256, 2)
hgemm3_kernel(const float* __restrict__ A, const float* __restrict__ W,
              const float* __restrict__ bias, float* __restrict__ C,
              int M, int N, int K)
{
    extern __shared__ char smem[];

    const int tid  = threadIdx.x;
    const int lane = tid & 31;
    const int wid  = tid >> 5;
    const int wm   = wid & 1;
    const int wn   = wid >> 1;
    const int m0   = blockIdx.y * 128;
    const int n0   = blockIdx.x * 128;

    // loader lane mapping: 4 passes of (32 rows x 32 floats)
    const int lr   = tid >> 3;
    const int lk   = (tid & 7) * 4;
    const int lc   = (tid & 7) >> 1;
    const int lsub = tid & 1;

    float4 pv[4];
    const float4 z4 = make_float4(0.f, 0.f, 0.f, 0.f);

    const unsigned s_u32 = (unsigned)__cvta_generic_to_shared(&smem[0]);

    unsigned aBase[4]; int aSw[4];
    const int kcA = lane >> 4;
#pragma unroll
    for (int mi = 0; mi < 4; mi++) {
        int r = wm * 64 + mi * 16 + (lane & 7) + ((lane >> 3) & 1) * 8;
        aBase[mi] = s_u32 + (unsigned)(r * 128);
        aSw[mi] = r & 7;
    }
    unsigned bBase[2]; int bSw[2];
    const int kcB = (lane >> 3) & 1;
#pragma unroll
    for (int pj = 0; pj < 2; pj++) {
        int r = wn * 32 + pj * 16 + ((lane >> 4) & 1) * 8 + (lane & 7);
        bBase[pj] = s_u32 + (unsigned)(TILE_BYTES + r * 128);
        bSw[pj] = r & 7;
    }

    float acc[4][4][4];
#pragma unroll
    for (int i = 0; i < 4; i++)
#pragma unroll
        for (int j = 0; j < 4; j++)
#pragma unroll
            for (int q = 0; q < 4; q++) acc[i][j][q] = 0.f;

    auto ldgA = [&](int k0) {
#pragma unroll
        for (int p = 0; p < 4; p++) {
            int m = lr + p * 32;
            pv[p] = *(const float4*)&A[(size_t)(m0 + m) * K + k0 + lk];
        }
    };
    auto ldgB = [&](int k0) {
#pragma unroll
        for (int p = 0; p < 4; p++) {
            int n = n0 + lr + p * 32;
            pv[p] = (n < N) ? *(const float4*)&W[(size_t)n * K + k0 + lk] : z4;
        }
    };

    auto sts_one = [&](int tileoff, int m, float4 v) {
        __nv_bfloat16 hx = __float2bfloat16(v.x);
        __nv_bfloat16 hy = __float2bfloat16(v.y);
        __nv_bfloat16 hz = __float2bfloat16(v.z);
        __nv_bfloat16 hw = __float2bfloat16(v.w);
        __nv_bfloat16 lx = __float2bfloat16(v.x - __bfloat162float(hx));
        __nv_bfloat16 ly = __float2bfloat16(v.y - __bfloat162float(hy));
        __nv_bfloat16 lz = __float2bfloat16(v.z - __bfloat162float(hz));
        __nv_bfloat16 lw = __float2bfloat16(v.w - __bfloat162float(hw));
        uint2 hi; hi.x = pack_bf16(hx, hy); hi.y = pack_bf16(hz, hw);
        uint2 lo; lo.x = pack_bf16(lx, ly); lo.y = pack_bf16(lz, lw);
        char* rowb = smem + tileoff + m * 128;
        int msw = m & 7;
        *(uint2*)(rowb + ((lc ^ msw) * 16) + lsub * 8)        = hi;
        *(uint2*)(rowb + (((lc + 4) ^ msw) * 16) + lsub * 8)  = lo;
    };
    auto stsA = [&](int buf) {
        int boff = buf * BUF_BYTES;
#pragma unroll
        for (int p = 0; p < 4; p++) sts_one(boff, lr + p * 32, pv[p]);
    };
    auto stsB = [&](int buf) {
        int boff = buf * BUF_BYTES + TILE_BYTES;
#pragma unroll
        for (int p = 0; p < 4; p++) sts_one(boff, lr + p * 32, pv[p]);
    };

    // register-lean mma phase for one half-k (K=16) step
    auto do_ks = [&](int ks, unsigned boff) {
        unsigned bh[4][2], bt[4][2];
#pragma unroll
        for (int pj = 0; pj < 2; pj++) {
            unsigned r0, r1, r2, r3;
            ldsm_x4(r0, r1, r2, r3,
                    bBase[pj] + boff + (unsigned)((((ks * 2 + kcB)) ^ bSw[pj]) * 16));
            bh[pj * 2][0] = r0; bh[pj * 2][1] = r1;
            bh[pj * 2 + 1][0] = r2; bh[pj * 2 + 1][1] = r3;
        }
#pragma unroll
        for (int pj = 0; pj < 2; pj++) {
            unsigned r0, r1, r2, r3;
            ldsm_x4(r0, r1, r2, r3,
                    bBase[pj] + boff + (unsigned)((((ks * 2 + kcB + 4)) ^ bSw[pj]) * 16));
            bt[pj * 2][0] = r0; bt[pj * 2][1] = r1;
            bt[pj * 2 + 1][0] = r2; bt[pj * 2 + 1][1] = r3;
        }
#pragma unroll
        for (int mi = 0; mi < 4; mi++) {
            unsigned a[4];
            ldsm_x4(a[0], a[1], a[2], a[3],
                    aBase[mi] + boff + (unsigned)((((ks * 2 + kcA)) ^ aSw[mi]) * 16));
#pragma unroll
            for (int nj = 0; nj < 4; nj++) mma16816(acc[mi][nj], a, bh[nj]);  // Ah*Bh
#pragma unroll
            for (int nj = 0; nj < 4; nj++) mma16816(acc[mi][nj], a, bt[nj]);  // Ah*Bl
            ldsm_x4(a[0], a[1], a[2], a[3],
                    aBase[mi] + boff + (unsigned)((((ks * 2 + kcA + 4)) ^ aSw[mi]) * 16));
#pragma unroll
            for (int nj = 0; nj < 4; nj++) mma16816(acc[mi][nj], a, bh[nj]);  // Al*Bh
        }
    };

    // prologue
    ldgA(0); stsA(0);
    ldgB(0); stsB(0);
    __syncthreads();

    const int nk = K >> 5;
    for (int it = 0; it < nk; it++) {
        const bool more = (it + 1) < nk;
        const unsigned boff = (unsigned)((it & 1) * BUF_BYTES);
        const int nb = (it + 1) & 1;

        if (more) ldgA((it + 1) * 32);
        do_ks(0, boff);
        if (more) { stsA(nb); ldgB((it + 1) * 32); }
        do_ks(1, boff);
        if (more) stsB(nb);
        __syncthreads();
    }

    // epilogue
    const int row0 = m0 + wm * 64 + (lane >> 2);
    const int col0 = n0 + wn * 32 + (lane & 3) * 2;
#pragma unroll
    for (int mi = 0; mi < 4; mi++) {
#pragma unroll
        for (int nj = 0; nj < 4; nj++) {
            int col = col0 + nj * 8;
            if (col < N) {
                float b0 = 0.f, b1 = 0.f;
                if (EPI >= 1) { b0 = bias[col]; b1 = bias[col + 1]; }
                float v0 = acc[mi][nj][0] + b0;
                float v1 = acc[mi][nj][1] + b1;
                float v2 = acc[mi][nj][2] + b0;
                float v3 = acc[mi][nj][3] + b1;
                if (EPI == 2) {
                    v0 = v0 / (1.f + expf(-v0));
                    v1 = v1 / (1.f + expf(-v1));
                    v2 = v2 / (1.f + expf(-v2));
                    v3 = v3 / (1.f + expf(-v3));
                }
                int r = row0 + mi * 16;
                float2 p0; p0.x = v0; p0.y = v1;
                float2 p1; p1.x = v2; p1.y = v3;
                *(float2*)&C[(size_t)r * N + col] = p0;
                *(float2*)&C[(size_t)(r + 8) * N + col] = p1;
            }
        }
    }
}

// ---------------- conv (anti-causal in natural order) + silu ----------------
__global__ void __launch_bounds__(256)
conv_silu_kernel(const float* __restrict__ zx, const float* __restrict__ cw,
                 const float* __restrict__ cb, float* __restrict__ xc)
{
    size_t idx = (size_t)blockIdx.x * blockDim.x + threadIdx.x;
    if (idx >= (size_t)BL * CONVD) return;
    int c  = (int)(idx % CONVD);
    int bl = (int)(idx / CONVD);
    int l  = bl % LL;

    float acc = cb[c];
    const float* base = zx + (size_t)bl * NPROJ + DINNER + c;
#pragma unroll
    for (int k = 0; k < 4; k++) {
        int off = 3 - k;
        if (l + off < LL) acc += cw[c * 4 + k] * base[(size_t)off * NPROJ];
    }
    acc = acc / (1.f + expf(-acc));
    xc[idx] = acc;
}

// ---------------- scan pass 1: segmented local scans (h_start = 0) ----------------
// grid 1024: blk = (bh<<4) | (phalf<<3) | seg. Each block: 512 reversed-time steps.
// Writes: y_local -> g_ys, per-t cum prod dA -> g_cum (phalf 0 only), end state -> g_hseg.
__global__ void __launch_bounds__(256)
scan_seg1_kernel(const float* __restrict__ zx, const float* __restrict__ xc,
                 const float* __restrict__ dt_bias, const float* __restrict__ A_log,
                 float* __restrict__ yout)
{
    int blk   = blockIdx.x;
    int seg   = blk & 7;
    int phalf = (blk >> 3) & 1;
    int bh    = blk >> 4;
    int b = bh >> 4, h = bh & 15;
    int tid = threadIdx.x;
    int pl = tid >> 3;
    int ng = tid & 7;
    int pg = phalf * 32 + pl;

    float Acoef = -expf(A_log[h]);
    float dtb   = dt_bias[h];

    __shared__ float sB[2][8][64], sC[2][8][64], sX[2][8][32];
    __shared__ float sdt[2][8], sDA[2][8];

    float hs[8];
#pragma unroll
    for (int j = 0; j < 8; j++) hs[j] = 0.f;

    float rBC[4], rX, rDR = 0.f;
    const int xt = tid >> 5, xj = tid & 31;
    const int sBeg = seg * SEGL;
    const int sEnd = sBeg + SEGL;

    float runP = 1.f;  // cumulative prod (used by tid 0 only)

    auto preload = [&](int s0) {
#pragma unroll
        for (int i = 0; i < 4; i++) {
            int e = tid + i * 256;
            int t = e >> 7, q = e & 127;
            int bl = b * LL + (LL - 1 - (s0 + t));
            rBC[i] = xc[(size_t)bl * CONVD + DINNER + q];
        }
        {
            int bl = b * LL + (LL - 1 - (s0 + xt));
            rX = xc[(size_t)bl * CONVD + h * HEADD + phalf * 32 + xj];
        }
        if (tid < 8) {
            int bl = b * LL + (LL - 1 - (s0 + tid));
            rDR = zx[(size_t)bl * NPROJ + (2 * DINNER + 2 * DSTATE) + h];
        }
    };
    auto commit_smem = [&](int buf) {
#pragma unroll
        for (int i = 0; i < 4; i++) {
            int e = tid + i * 256;
            int t = e >> 7, q = e & 127;
            if (q < 64) sB[buf][t][q] = rBC[i]; else sC[buf][t][q - 64] = rBC[i];
        }
        sX[buf][xt][xj] = rX;
        if (tid < 8) {
            float dr = rDR + dtb;
            float dt = (dr > 20.f) ? dr : log1pf(expf(dr));
            sdt[buf][tid] = dt;
            sDA[buf][tid] = expf(dt * Acoef);
        }
    };

    preload(sBeg);
    commit_smem(0);
    __syncthreads();

    for (int s0 = sBeg; s0 < sEnd; s0 += 8) {
        int buf = ((s0 - sBeg) >> 3) & 1;
        bool more = (s0 + 8) < sEnd;
        if (more) preload(s0 + 8);

        // cum prod of dA (one thread, phalf 0 only)
        if (phalf == 0 && tid == 0) {
            float* cw = &g_cum[(size_t)bh * LL + s0];
#pragma unroll
            for (int t = 0; t < 8; t++) { runP *= sDA[buf][t]; cw[t] = runP; }
        }

#pragma unroll
        for (int t = 0; t < 8; t++) {
            float dA  = sDA[buf][t];
            float dtx = sdt[buf][t] * sX[buf][t][pl];
            float4 bb0 = *(const float4*)&sB[buf][t][ng * 8];
            float4 bb1 = *(const float4*)&sB[buf][t][ng * 8 + 4];
            hs[0] = hs[0] * dA + dtx * bb0.x;
            hs[1] = hs[1] * dA + dtx * bb0.y;
            hs[2] = hs[2] * dA + dtx * bb0.z;
            hs[3] = hs[3] * dA + dtx * bb0.w;
            hs[4] = hs[4] * dA + dtx * bb1.x;
            hs[5] = hs[5] * dA + dtx * bb1.y;
            hs[6] = hs[6] * dA + dtx * bb1.z;
            hs[7] = hs[7] * dA + dtx * bb1.w;
            float4 cc0 = *(const float4*)&sC[buf][t][ng * 8];
            float4 cc1 = *(const float4*)&sC[buf][t][ng * 8 + 4];
            float yp = hs[0] * cc0.x + hs[1] * cc0.y + hs[2] * cc0.z + hs[3] * cc0.w
                     + hs[4] * cc1.x + hs[5] * cc1.y + hs[6] * cc1.z + hs[7] * cc1.w;
            yp += __shfl_xor_sync(0xffffffffu, yp, 1);
            yp += __shfl_xor_sync(0xffffffffu, yp, 2);
            yp += __shfl_xor_sync(0xffffffffu, yp, 4);
            if (ng == 0) {
                int l = LL - 1 - (s0 + t);
                yout[((size_t)(b * LL + l)) * DINNER + h * HEADD + pg] = yp;
            }
        }
        if (more) commit_smem(buf ^ 1);
        __syncthreads();
    }

    // store end state
    {
        float* hd = &g_hseg[((size_t)(bh * 2 + phalf) * SSEG + seg) * 2048 + pl * 64 + ng * 8];
#pragma unroll
        for (int j = 0; j < 8; j++) hd[j] = hs[j];
    }
}

// ---------------- scan pass 2: combine segment boundary states ----------------
// grid 64 (bh); h_start[0]=0; h_start[s] = P[s-1]*h_start[s-1] + hend[s-1]
__global__ void __launch_bounds__(256)
scan_comb_kernel()
{
    int bh = blockIdx.x;
    int tid = threadIdx.x;
    float hst[16];
#pragma unroll
    for (int i = 0; i < 16; i++) hst[i] = 0.f;

    for (int seg = 0; seg < SSEG; seg++) {
        float P = g_cum[(size_t)bh * LL + seg * SEGL + SEGL - 1];
#pragma unroll
        for (int i = 0; i < 16; i++) {
            int e = tid + i * 256;            // e in [0,4096)
            int ph = e >> 11;
            int rem = e & 2047;
            size_t base = ((size_t)(bh * 2 + ph) * SSEG + seg) * 2048 + rem;
            g_hst[base] = hst[i];
            hst[i] = P * hst[i] + g_hseg[base];
        }
    }
}

// ---------------- scan pass 3: y += cum(t) * (C_t . h_start_seg) ----------------
__global__ void __launch_bounds__(256)
scan_fix_kernel(const float* __restrict__ xc, float* __restrict__ yout)
{
    int blk   = blockIdx.x;
    int seg   = blk & 7;
    if (seg == 0) return;
    int phalf = (blk >> 3) & 1;
    int bh    = blk >> 4;
    int b = bh >> 4, h = bh & 15;
    int tid = threadIdx.x;
    int pl = tid >> 3;
    int ng = tid & 7;
    int pg = phalf * 32 + pl;

    float hs[8];
    {
        const float* hp = &g_hst[((size_t)(bh * 2 + phalf) * SSEG + seg) * 2048 + pl * 64 + ng * 8];
#pragma unroll
        for (int j = 0; j < 8; j++) hs[j] = hp[j];
    }

    __shared__ float sC[8][64];
    __shared__ float sCum[8];
    const int sBeg = seg * SEGL;

    for (int s0 = sBeg; s0 < sBeg + SEGL; s0 += 8) {
#pragma unroll
        for (int i = 0; i < 2; i++) {
            int e = tid + i * 256;
            int t = e >> 6, q = e & 63;
            int bl = b * LL + (LL - 1 - (s0 + t));
            sC[t][q] = xc[(size_t)bl * CONVD + DINNER + DSTATE + q];
        }
        if (tid < 8) sCum[tid] = g_cum[(size_t)bh * LL + s0 + tid];
        __syncthreads();

#pragma unroll
        for (int t = 0; t < 8; t++) {
            float4 cc0 = *(const float4*)&sC[t][ng * 8];
            float4 cc1 = *(const float4*)&sC[t][ng * 8 + 4];
            float yp = hs[0] * cc0.x + hs[1] * cc0.y + hs[2] * cc0.z + hs[3] * cc0.w
                     + hs[4] * cc1.x + hs[5] * cc1.y + hs[6] * cc1.z + hs[7] * cc1.w;
            yp += __shfl_xor_sync(0xffffffffu, yp, 1);
            yp += __shfl_xor_sync(0xffffffffu, yp, 2);
            yp += __shfl_xor_sync(0xffffffffu, yp, 4);
            if (ng == 0) {
                int l = LL - 1 - (s0 + t);
                size_t idx = ((size_t)(b * LL + l)) * DINNER + h * HEADD + pg;
                yout[idx] += sCum[t] * yp;
            }
        }
        __syncthreads();
    }
}

// ---------------- block reduction helper ----------------
__device__ __forceinline__ float block_reduce_sum(float v) {
    __shared__ float sred[32];
    int lane = threadIdx.x & 31, w = threadIdx.x >> 5;
#pragma unroll
    for (int o = 16; o; o >>= 1) v += __shfl_xor_sync(0xffffffffu, v, o);
    if (lane == 0) sred[w] = v;
    __syncthreads();
    int nw = blockDim.x >> 5;
    float r = (threadIdx.x < nw) ? sred[threadIdx.x] : 0.f;
    if (w == 0) {
#pragma unroll
        for (int o = 16; o; o >>= 1) r += __shfl_xor_sync(0xffffffffu, r, o);
        if (lane == 0) sred[0] = r;
    }
    __syncthreads();
    float out = sred[0];
    __syncthreads();
    return out;
}

// ---------------- gate (y + D*xh) * silu(z), rmsnorm, * rms_w ----------------
__global__ void __launch_bounds__(256)
gate_rms_kernel(const float* __restrict__ ys, const float* __restrict__ xc,
                const float* __restrict__ zx, const float* __restrict__ Dv,
                const float* __restrict__ rw, float* __restrict__ yb)
{
    int row = blockIdx.x;
    size_t oy = (size_t)row * DINNER, oc = (size_t)row * CONVD, oz = (size_t)row * NPROJ;
    float v[4];
    float ss = 0.f;
#pragma unroll
    for (int i = 0; i < 4; i++) {
        int c = threadIdx.x + i * 256;
        float z = zx[oz + c];
        float sz = z / (1.f + expf(-z));
        float val = (ys[oy + c] + Dv[c >> 6] * xc[oc + c]) * sz;
        v[i] = val;
        ss += val * val;
    }
    ss = block_reduce_sum(ss);
    float r = rsqrtf(ss * (1.f / (float)DINNER) + 1e-5f);
#pragma unroll
    for (int i = 0; i < 4; i++) {
        int c = threadIdx.x + i * 256;
        yb[oy + c] = v[i] * r * rw[c];
    }
}

// ---------------- layernorm over 512 ----------------
__global__ void __launch_bounds__(128)
layernorm_kernel(const float* __restrict__ x, const float* __restrict__ g,
                 const float* __restrict__ bpar, float* __restrict__ out)
{
    int row = blockIdx.x;
    size_t o = (size_t)row * DMODEL;
    float v[4];
    float s = 0.f;
#pragma unroll
    for (int i = 0; i < 4; i++) {
        int c = threadIdx.x + i * 128;
        v[i] = x[o + c];
        s += v[i];
    }
    s = block_reduce_sum(s);
    float m = s * (1.f / (float)DMODEL);
    float ss = 0.f;
#pragma unroll
    for (int i = 0; i < 4; i++) { float d = v[i] - m; ss += d * d; }
    ss = block_reduce_sum(ss);
    float r = rsqrtf(ss * (1.f / (float)DMODEL) + 1e-5f);
#pragma unroll
    for (int i = 0; i < 4; i++) {
        int c = threadIdx.x + i * 128;
        out[o + c] = (v[i] - m) * r * g[c] + bpar[c];
    }
}

// ---------------- w1eff = w1[:, :512] + w1[:, 512:] ----------------
__global__ void __launch_bounds__(256)
w1eff_kernel(const float* __restrict__ w1, float* __restrict__ w1e)
{
    int idx = blockIdx.x * blockDim.x + threadIdx.x;
    if (idx >= 1024 * 512) return;
    int n = idx / 512, k = idx % 512;
    w1e[idx] = w1[n * 1024 + k] + w1[n * 1024 + 512 + k];
}

// ---------------- launch ----------------
extern "C" void kernel_launch(void* const* d_in, const int* in_sizes, int n_in,
                              void* d_out, int out_size)
{
    const float* x         = (const float*)d_in[0];
    const float* in_proj_w = (const float*)d_in[1];
    const float* conv_w    = (const float*)d_in[2];
    const float* conv_b    = (const float*)d_in[3];
    const float* dt_bias   = (const float*)d_in[4];
    const float* A_log     = (const float*)d_in[5];
    const float* Dv        = (const float*)d_in[6];
    const float* rms_w     = (const float*)d_in[7];
    const float* out_proj  = (const float*)d_in[8];
    const float* ln_g      = (const float*)d_in[9];
    const float* ln_b      = (const float*)d_in[10];
    const float* w1        = (const float*)d_in[11];
    const float* b1        = (const float*)d_in[12];
    const float* w2        = (const float*)d_in[13];
    const float* b2        = (const float*)d_in[14];
    float* outp            = (float*)d_out;

    float *p_zx, *p_xc, *p_ys, *p_yb, *p_y2, *p_yln, *p_h1, *p_w1e;
    cudaGetSymbolAddress((void**)&p_zx,  g_zx);
    cudaGetSymbolAddress((void**)&p_xc,  g_xc);
    cudaGetSymbolAddress((void**)&p_ys,  g_ys);
    cudaGetSymbolAddress((void**)&p_yb,  g_yb);
    cudaGetSymbolAddress((void**)&p_y2,  g_y2);
    cudaGetSymbolAddress((void**)&p_yln, g_yln);
    cudaGetSymbolAddress((void**)&p_h1,  g_h1);
    cudaGetSymbolAddress((void**)&p_w1e, g_w1e);

    static bool attr_done = false;
    if (!attr_done) {
        cudaFuncSetAttribute(hgemm3_kernel<0>, cudaFuncAttributeMaxDynamicSharedMemorySize, GSM_BYTES);
        cudaFuncSetAttribute(hgemm3_kernel<1>, cudaFuncAttributeMaxDynamicSharedMemorySize, GSM_BYTES);
        cudaFuncSetAttribute(hgemm3_kernel<2>, cudaFuncAttributeMaxDynamicSharedMemorySize, GSM_BYTES);
        attr_done = true;
    }

    w1eff_kernel<<<(1024 * 512 + 255) / 256, 256>>>(w1, p_w1e);

    // 1) in_proj
    {
        dim3 grid((NPROJ + 127) / 128, BL / 128);
        hgemm3_kernel<0><<<grid, 256, GSM_BYTES>>>(x, in_proj_w, nullptr, p_zx, BL, NPROJ, DMODEL);
    }
    // 2) conv + silu
    {
        size_t tot = (size_t)BL * CONVD;
        conv_silu_kernel<<<(unsigned)((tot + 255) / 256), 256>>>(p_zx, conv_w, conv_b, p_xc);
    }
    // 3) segmented selective scan
    scan_seg1_kernel<<<64 * 2 * SSEG, 256>>>(p_zx, p_xc, dt_bias, A_log, p_ys);
    scan_comb_kernel<<<64, 256>>>();
    scan_fix_kernel<<<64 * 2 * SSEG, 256>>>(p_xc, p_ys);
    // 4) gate + rmsnorm
    gate_rms_kernel<<<BL, 256>>>(p_ys, p_xc, p_zx, Dv, rms_w, p_yb);
    // 5) out_proj
    {
        dim3 grid(DMODEL / 128, BL / 128);
        hgemm3_kernel<0><<<grid, 256, GSM_BYTES>>>(p_yb, out_proj, nullptr, p_y2, BL, DMODEL, DINNER);
    }
    // 6) layernorm
    layernorm_kernel<<<BL, 128>>>(p_y2, ln_g, ln_b, p_yln);
    // 7) mlp hidden
    {
        dim3 grid(DINNER / 128, BL / 128);
        hgemm3_kernel<2><<<grid, 256, GSM_BYTES>>>(p_yln, p_w1e, b1, p_h1, BL, DINNER, DMODEL);
    }
    // 8) output
    {
        dim3 grid(DMODEL / 128, BL / 128);
        hgemm3_kernel<1><<<grid, 256, GSM_BYTES>>>(p_h1, w2, b2, outp, BL, DMODEL, DINNER);
    }
}

// round 6
// speedup vs baseline: 2.7386x; 1.2147x over previous
#include <cuda_runtime.h>
#include <cuda_bf16.h>
#include <math.h>
#include <stdint.h>

// ---------------- problem constants ----------------
#define BB      4
#define LL      4096
#define DMODEL  512
#define DINNER  1024
#define DSTATE  64
#define HEADD   64
#define NHEADS  16
#define CONVD   1152        // DINNER + 2*DSTATE
#define NPROJ   2192        // 2*DINNER + 2*DSTATE + NHEADS
#define BL      (BB*LL)     // 16384

// scan segmentation
#define SSEG    8
#define SEGL    (LL / SSEG)   // 512

// ---------------- scratch (device globals; no runtime alloc allowed) ----------------
__device__ float g_zx [(size_t)BL * NPROJ];
__device__ float g_xc [(size_t)BL * CONVD];
__device__ float g_ys [(size_t)BL * DINNER];
__device__ float g_yb [(size_t)BL * DINNER];
__device__ float g_y2 [(size_t)BL * DMODEL];
__device__ float g_yln[(size_t)BL * DMODEL];
__device__ float g_h1 [(size_t)BL * DINNER];
__device__ float g_w1e[1024 * 512];
__device__ float g_hseg[64 * SSEG * 4096];      // per (b,h,seg): 64p x 64n end-state
__device__ float g_hst [64 * SSEG * 4096];      // per-segment start states
__device__ float g_cum [64 * LL];               // per (b,h,s): cum prod dA within segment

// ================= tensor-core split-bf16 GEMM (mma.sync) =================
__device__ __forceinline__ unsigned pack_bf16(__nv_bfloat16 a, __nv_bfloat16 b) {
    unsigned short ua = *(unsigned short*)&a;
    unsigned short ub = *(unsigned short*)&b;
    return (unsigned)ua | ((unsigned)ub << 16);
}

__device__ __forceinline__ void ldsm_x4(unsigned &r0, unsigned &r1,
                                        unsigned &r2, unsigned &r3, unsigned addr) {
    asm volatile("ldmatrix.sync.aligned.m8n8.x4.shared.b16 {%0,%1,%2,%3}, [%4];"
                 : "=r"(r0), "=r"(r1), "=r"(r2), "=r"(r3) : "r"(addr));
}

__device__ __forceinline__ void mma16816(float* c, const unsigned* a, const unsigned* b) {
    asm volatile(
        "mma.sync.aligned.m16n8k16.row.col.f32.bf16.bf16.f32 "
        "{%0,%1,%2,%3}, {%4,%5,%6,%7}, {%8,%9}, {%0,%1,%2,%3};"
        : "+f"(c[0]), "+f"(c[1]), "+f"(c[2]), "+f"(c[3])
        : "r"(a[0]), "r"(a[1]), "r"(a[2]), "r"(a[3]), "r"(b[0]), "r"(b[1]));
}

#define TILE_BYTES   16384
#define BUF_BYTES    (2 * TILE_BYTES)
#define GSM_BYTES    (2 * BUF_BYTES)

// EPI: 0 = none, 1 = +bias, 2 = +bias then silu
template<int EPI>
__global__ void __launch_bounds__(256, 2)
hgemm3_kernel(const float* __restrict__ A, const float* __restrict__ W,
              const float* __restrict__ bias, float* __restrict__ C,
              int M, int N, int K)
{
    extern __shared__ char smem[];

    const int tid  = threadIdx.x;
    const int lane = tid & 31;
    const int wid  = tid >> 5;
    const int wm   = wid & 1;
    const int wn   = wid >> 1;
    const int m0   = blockIdx.y * 128;
    const int n0   = blockIdx.x * 128;

    const int lr   = tid >> 3;
    const int lk   = (tid & 7) * 4;
    const int lc   = (tid & 7) >> 1;
    const int lsub = tid & 1;

    float4 pv[4];
    const float4 z4 = make_float4(0.f, 0.f, 0.f, 0.f);

    const unsigned s_u32 = (unsigned)__cvta_generic_to_shared(&smem[0]);

    unsigned aBase[4]; int aSw[4];
    const int kcA = lane >> 4;
#pragma unroll
    for (int mi = 0; mi < 4; mi++) {
        int r = wm * 64 + mi * 16 + (lane & 7) + ((lane >> 3) & 1) * 8;
        aBase[mi] = s_u32 + (unsigned)(r * 128);
        aSw[mi] = r & 7;
    }
    unsigned bBase[2]; int bSw[2];
    const int kcB = (lane >> 3) & 1;
#pragma unroll
    for (int pj = 0; pj < 2; pj++) {
        int r = wn * 32 + pj * 16 + ((lane >> 4) & 1) * 8 + (lane & 7);
        bBase[pj] = s_u32 + (unsigned)(TILE_BYTES + r * 128);
        bSw[pj] = r & 7;
    }

    float acc[4][4][4];
#pragma unroll
    for (int i = 0; i < 4; i++)
#pragma unroll
        for (int j = 0; j < 4; j++)
#pragma unroll
            for (int q = 0; q < 4; q++) acc[i][j][q] = 0.f;

    auto ldgA = [&](int k0) {
#pragma unroll
        for (int p = 0; p < 4; p++) {
            int m = lr + p * 32;
            pv[p] = *(const float4*)&A[(size_t)(m0 + m) * K + k0 + lk];
        }
    };
    auto ldgB = [&](int k0) {
#pragma unroll
        for (int p = 0; p < 4; p++) {
            int n = n0 + lr + p * 32;
            pv[p] = (n < N) ? *(const float4*)&W[(size_t)n * K + k0 + lk] : z4;
        }
    };

    auto sts_one = [&](int tileoff, int m, float4 v) {
        __nv_bfloat16 hx = __float2bfloat16(v.x);
        __nv_bfloat16 hy = __float2bfloat16(v.y);
        __nv_bfloat16 hz = __float2bfloat16(v.z);
        __nv_bfloat16 hw = __float2bfloat16(v.w);
        __nv_bfloat16 lx = __float2bfloat16(v.x - __bfloat162float(hx));
        __nv_bfloat16 ly = __float2bfloat16(v.y - __bfloat162float(hy));
        __nv_bfloat16 lz = __float2bfloat16(v.z - __bfloat162float(hz));
        __nv_bfloat16 lw = __float2bfloat16(v.w - __bfloat162float(hw));
        uint2 hi; hi.x = pack_bf16(hx, hy); hi.y = pack_bf16(hz, hw);
        uint2 lo; lo.x = pack_bf16(lx, ly); lo.y = pack_bf16(lz, lw);
        char* rowb = smem + tileoff + m * 128;
        int msw = m & 7;
        *(uint2*)(rowb + ((lc ^ msw) * 16) + lsub * 8)        = hi;
        *(uint2*)(rowb + (((lc + 4) ^ msw) * 16) + lsub * 8)  = lo;
    };
    auto stsA = [&](int buf) {
        int boff = buf * BUF_BYTES;
#pragma unroll
        for (int p = 0; p < 4; p++) sts_one(boff, lr + p * 32, pv[p]);
    };
    auto stsB = [&](int buf) {
        int boff = buf * BUF_BYTES + TILE_BYTES;
#pragma unroll
        for (int p = 0; p < 4; p++) sts_one(boff, lr + p * 32, pv[p]);
    };

    auto do_ks = [&](int ks, unsigned boff) {
        unsigned bh[4][2], bt[4][2];
#pragma unroll
        for (int pj = 0; pj < 2; pj++) {
            unsigned r0, r1, r2, r3;
            ldsm_x4(r0, r1, r2, r3,
                    bBase[pj] + boff + (unsigned)((((ks * 2 + kcB)) ^ bSw[pj]) * 16));
            bh[pj * 2][0] = r0; bh[pj * 2][1] = r1;
            bh[pj * 2 + 1][0] = r2; bh[pj * 2 + 1][1] = r3;
        }
#pragma unroll
        for (int pj = 0; pj < 2; pj++) {
            unsigned r0, r1, r2, r3;
            ldsm_x4(r0, r1, r2, r3,
                    bBase[pj] + boff + (unsigned)((((ks * 2 + kcB + 4)) ^ bSw[pj]) * 16));
            bt[pj * 2][0] = r0; bt[pj * 2][1] = r1;
            bt[pj * 2 + 1][0] = r2; bt[pj * 2 + 1][1] = r3;
        }
#pragma unroll
        for (int mi = 0; mi < 4; mi++) {
            unsigned a[4];
            ldsm_x4(a[0], a[1], a[2], a[3],
                    aBase[mi] + boff + (unsigned)((((ks * 2 + kcA)) ^ aSw[mi]) * 16));
#pragma unroll
            for (int nj = 0; nj < 4; nj++) mma16816(acc[mi][nj], a, bh[nj]);
#pragma unroll
            for (int nj = 0; nj < 4; nj++) mma16816(acc[mi][nj], a, bt[nj]);
            ldsm_x4(a[0], a[1], a[2], a[3],
                    aBase[mi] + boff + (unsigned)((((ks * 2 + kcA + 4)) ^ aSw[mi]) * 16));
#pragma unroll
            for (int nj = 0; nj < 4; nj++) mma16816(acc[mi][nj], a, bh[nj]);
        }
    };

    ldgA(0); stsA(0);
    ldgB(0); stsB(0);
    __syncthreads();

    const int nk = K >> 5;
    for (int it = 0; it < nk; it++) {
        const bool more = (it + 1) < nk;
        const unsigned boff = (unsigned)((it & 1) * BUF_BYTES);
        const int nb = (it + 1) & 1;

        if (more) ldgA((it + 1) * 32);
        do_ks(0, boff);
        if (more) { stsA(nb); ldgB((it + 1) * 32); }
        do_ks(1, boff);
        if (more) stsB(nb);
        __syncthreads();
    }

    const int row0 = m0 + wm * 64 + (lane >> 2);
    const int col0 = n0 + wn * 32 + (lane & 3) * 2;
#pragma unroll
    for (int mi = 0; mi < 4; mi++) {
#pragma unroll
        for (int nj = 0; nj < 4; nj++) {
            int col = col0 + nj * 8;
            if (col < N) {
                float b0 = 0.f, b1 = 0.f;
                if (EPI >= 1) { b0 = bias[col]; b1 = bias[col + 1]; }
                float v0 = acc[mi][nj][0] + b0;
                float v1 = acc[mi][nj][1] + b1;
                float v2 = acc[mi][nj][2] + b0;
                float v3 = acc[mi][nj][3] + b1;
                if (EPI == 2) {
                    v0 = v0 / (1.f + expf(-v0));
                    v1 = v1 / (1.f + expf(-v1));
                    v2 = v2 / (1.f + expf(-v2));
                    v3 = v3 / (1.f + expf(-v3));
                }
                int r = row0 + mi * 16;
                float2 p0; p0.x = v0; p0.y = v1;
                float2 p1; p1.x = v2; p1.y = v3;
                *(float2*)&C[(size_t)r * N + col] = p0;
                *(float2*)&C[(size_t)(r + 8) * N + col] = p1;
            }
        }
    }
}

// ---------------- conv (anti-causal in natural order) + silu ----------------
__global__ void __launch_bounds__(256)
conv_silu_kernel(const float* __restrict__ zx, const float* __restrict__ cw,
                 const float* __restrict__ cb, float* __restrict__ xc)
{
    size_t idx = (size_t)blockIdx.x * blockDim.x + threadIdx.x;
    if (idx >= (size_t)BL * CONVD) return;
    int c  = (int)(idx % CONVD);
    int bl = (int)(idx / CONVD);
    int l  = bl % LL;

    float acc = cb[c];
    const float* base = zx + (size_t)bl * NPROJ + DINNER + c;
#pragma unroll
    for (int k = 0; k < 4; k++) {
        int off = 3 - k;
        if (l + off < LL) acc += cw[c * 4 + k] * base[(size_t)off * NPROJ];
    }
    acc = acc / (1.f + expf(-acc));
    xc[idx] = acc;
}

// ---------------- scan pass 1: segmented local scans ----------------
// grid 512: blk = bh*SSEG + seg. 256 threads: pl = tid>>2 (64 p), ng = tid&3.
// Thread owns 16 n-states: n(j) = (j>>2)*16 + ng*4 + (j&3).
// Batched shfl reduction across the 8-t chunk.
__global__ void __launch_bounds__(256)
scan_seg1_kernel(const float* __restrict__ zx, const float* __restrict__ xc,
                 const float* __restrict__ dt_bias, const float* __restrict__ A_log,
                 float* __restrict__ yout)
{
    int blk = blockIdx.x;
    int seg = blk & (SSEG - 1);
    int bh  = blk / SSEG;
    int b = bh >> 4, h = bh & 15;
    int tid = threadIdx.x;
    int pl = tid >> 2;            // 0..63
    int ng = tid & 3;             // 0..3

    float Acoef = -expf(A_log[h]);
    float dtb   = dt_bias[h];

    __shared__ float sB[2][8][64], sC[2][8][64], sX[2][8][64];
    __shared__ float sdt[2][8], sDA[2][8];

    float hs[16];
#pragma unroll
    for (int j = 0; j < 16; j++) hs[j] = 0.f;

    float rBC[4], rX[2], rDR = 0.f;
    const int sBeg = seg * SEGL;
    const int sEnd = sBeg + SEGL;

    float runP = 1.f;

    auto preload = [&](int s0) {
#pragma unroll
        for (int i = 0; i < 4; i++) {
            int e = tid + i * 256;
            int t = e >> 7, q = e & 127;
            int bl = b * LL + (LL - 1 - (s0 + t));
            rBC[i] = xc[(size_t)bl * CONVD + DINNER + q];
        }
#pragma unroll
        for (int i = 0; i < 2; i++) {
            int e = tid + i * 256;
            int t = e >> 6, j = e & 63;
            int bl = b * LL + (LL - 1 - (s0 + t));
            rX[i] = xc[(size_t)bl * CONVD + h * HEADD + j];
        }
        if (tid < 8) {
            int bl = b * LL + (LL - 1 - (s0 + tid));
            rDR = zx[(size_t)bl * NPROJ + (2 * DINNER + 2 * DSTATE) + h];
        }
    };
    auto commit_smem = [&](int buf) {
#pragma unroll
        for (int i = 0; i < 4; i++) {
            int e = tid + i * 256;
            int t = e >> 7, q = e & 127;
            if (q < 64) sB[buf][t][q] = rBC[i]; else sC[buf][t][q - 64] = rBC[i];
        }
#pragma unroll
        for (int i = 0; i < 2; i++) {
            int e = tid + i * 256;
            int t = e >> 6, j = e & 63;
            sX[buf][t][j] = rX[i];
        }
        if (tid < 8) {
            float dr = rDR + dtb;
            float dt = (dr > 20.f) ? dr : log1pf(expf(dr));
            sdt[buf][tid] = dt;
            sDA[buf][tid] = expf(dt * Acoef);
        }
    };

    preload(sBeg);
    commit_smem(0);
    __syncthreads();

    for (int s0 = sBeg; s0 < sEnd; s0 += 8) {
        int buf = ((s0 - sBeg) >> 3) & 1;
        bool more = (s0 + 8) < sEnd;
        if (more) preload(s0 + 8);

        if (tid == 0) {
            float* cw = &g_cum[(size_t)bh * LL + s0];
#pragma unroll
            for (int t = 0; t < 8; t++) { runP *= sDA[buf][t]; cw[t] = runP; }
        }

        float yv[8];
#pragma unroll
        for (int t = 0; t < 8; t++) {
            float dA  = sDA[buf][t];
            float dtx = sdt[buf][t] * sX[buf][t][pl];
            float yp = 0.f;
#pragma unroll
            for (int u = 0; u < 4; u++) {
                float4 bb = *(const float4*)&sB[buf][t][u * 16 + ng * 4];
                hs[u*4+0] = hs[u*4+0] * dA + dtx * bb.x;
                hs[u*4+1] = hs[u*4+1] * dA + dtx * bb.y;
                hs[u*4+2] = hs[u*4+2] * dA + dtx * bb.z;
                hs[u*4+3] = hs[u*4+3] * dA + dtx * bb.w;
            }
#pragma unroll
            for (int u = 0; u < 4; u++) {
                float4 cc = *(const float4*)&sC[buf][t][u * 16 + ng * 4];
                yp += hs[u*4+0] * cc.x + hs[u*4+1] * cc.y
                    + hs[u*4+2] * cc.z + hs[u*4+3] * cc.w;
            }
            yv[t] = yp;
        }
        // batched 2-level reduction over ng (lanes differing in bits 0,1)
#pragma unroll
        for (int t = 0; t < 8; t++) yv[t] += __shfl_xor_sync(0xffffffffu, yv[t], 1);
#pragma unroll
        for (int t = 0; t < 8; t++) yv[t] += __shfl_xor_sync(0xffffffffu, yv[t], 2);
        if (ng == 0) {
#pragma unroll
            for (int t = 0; t < 8; t++) {
                int l = LL - 1 - (s0 + t);
                yout[((size_t)(b * LL + l)) * DINNER + h * HEADD + pl] = yv[t];
            }
        }

        if (more) commit_smem(buf ^ 1);
        __syncthreads();
    }

    // store end state: layout [pl*64 + n]
    {
        float* hd = &g_hseg[((size_t)blk) * 4096 + pl * 64];
#pragma unroll
        for (int j = 0; j < 16; j++) {
            int n = ((j >> 2) << 4) + (ng << 2) + (j & 3);
            hd[n] = hs[j];
        }
    }
}

// ---------------- scan pass 2: combine segment boundary states ----------------
__global__ void __launch_bounds__(256)
scan_comb_kernel()
{
    int bh = blockIdx.x;
    int tid = threadIdx.x;
    float hst[16];
#pragma unroll
    for (int i = 0; i < 16; i++) hst[i] = 0.f;

    for (int seg = 0; seg < SSEG; seg++) {
        float P = g_cum[(size_t)bh * LL + seg * SEGL + SEGL - 1];
#pragma unroll
        for (int i = 0; i < 16; i++) {
            int e = tid + i * 256;            // e in [0,4096)
            size_t base = ((size_t)(bh * SSEG + seg)) * 4096 + e;
            g_hst[base] = hst[i];
            hst[i] = P * hst[i] + g_hseg[base];
        }
    }
}

// ---------------- scan pass 3: y += cum(t) * (C_t . h_start_seg) ----------------
__global__ void __launch_bounds__(256)
scan_fix_kernel(const float* __restrict__ xc, float* __restrict__ yout)
{
    int blk = blockIdx.x;
    int seg = blk & (SSEG - 1);
    if (seg == 0) return;
    int bh  = blk / SSEG;
    int b = bh >> 4, h = bh & 15;
    int tid = threadIdx.x;
    int pl = tid >> 2;
    int ng = tid & 3;

    float hs[16];
    {
        const float* hp = &g_hst[((size_t)blk) * 4096 + pl * 64];
#pragma unroll
        for (int j = 0; j < 16; j++) {
            int n = ((j >> 2) << 4) + (ng << 2) + (j & 3);
            hs[j] = hp[n];
        }
    }

    __shared__ float sC[8][64];
    __shared__ float sCum[8];
    const int sBeg = seg * SEGL;

    for (int s0 = sBeg; s0 < sBeg + SEGL; s0 += 8) {
#pragma unroll
        for (int i = 0; i < 2; i++) {
            int e = tid + i * 256;
            int t = e >> 6, q = e & 63;
            int bl = b * LL + (LL - 1 - (s0 + t));
            sC[t][q] = xc[(size_t)bl * CONVD + DINNER + DSTATE + q];
        }
        if (tid < 8) sCum[tid] = g_cum[(size_t)bh * LL + s0 + tid];
        __syncthreads();

        float yv[8];
#pragma unroll
        for (int t = 0; t < 8; t++) {
            float yp = 0.f;
#pragma unroll
            for (int u = 0; u < 4; u++) {
                float4 cc = *(const float4*)&sC[t][u * 16 + ng * 4];
                yp += hs[u*4+0] * cc.x + hs[u*4+1] * cc.y
                    + hs[u*4+2] * cc.z + hs[u*4+3] * cc.w;
            }
            yv[t] = yp * sCum[t];
        }
#pragma unroll
        for (int t = 0; t < 8; t++) yv[t] += __shfl_xor_sync(0xffffffffu, yv[t], 1);
#pragma unroll
        for (int t = 0; t < 8; t++) yv[t] += __shfl_xor_sync(0xffffffffu, yv[t], 2);
        if (ng == 0) {
#pragma unroll
            for (int t = 0; t < 8; t++) {
                int l = LL - 1 - (s0 + t);
                size_t idx = ((size_t)(b * LL + l)) * DINNER + h * HEADD + pl;
                yout[idx] += yv[t];
            }
        }
        __syncthreads();
    }
}

// ---------------- block reduction helper ----------------
__device__ __forceinline__ float block_reduce_sum(float v) {
    __shared__ float sred[32];
    int lane = threadIdx.x & 31, w = threadIdx.x >> 5;
#pragma unroll
    for (int o = 16; o; o >>= 1) v += __shfl_xor_sync(0xffffffffu, v, o);
    if (lane == 0) sred[w] = v;
    __syncthreads();
    int nw = blockDim.x >> 5;
    float r = (threadIdx.x < nw) ? sred[threadIdx.x] : 0.f;
    if (w == 0) {
#pragma unroll
        for (int o = 16; o; o >>= 1) r += __shfl_xor_sync(0xffffffffu, r, o);
        if (lane == 0) sred[0] = r;
    }
    __syncthreads();
    float out = sred[0];
    __syncthreads();
    return out;
}

// ---------------- gate (y + D*xh) * silu(z), rmsnorm, * rms_w ----------------
__global__ void __launch_bounds__(256)
gate_rms_kernel(const float* __restrict__ ys, const float* __restrict__ xc,
                const float* __restrict__ zx, const float* __restrict__ Dv,
                const float* __restrict__ rw, float* __restrict__ yb)
{
    int row = blockIdx.x;
    size_t oy = (size_t)row * DINNER, oc = (size_t)row * CONVD, oz = (size_t)row * NPROJ;
    float v[4];
    float ss = 0.f;
#pragma unroll
    for (int i = 0; i < 4; i++) {
        int c = threadIdx.x + i * 256;
        float z = zx[oz + c];
        float sz = z / (1.f + expf(-z));
        float val = (ys[oy + c] + Dv[c >> 6] * xc[oc + c]) * sz;
        v[i] = val;
        ss += val * val;
    }
    ss = block_reduce_sum(ss);
    float r = rsqrtf(ss * (1.f / (float)DINNER) + 1e-5f);
#pragma unroll
    for (int i = 0; i < 4; i++) {
        int c = threadIdx.x + i * 256;
        yb[oy + c] = v[i] * r * rw[c];
    }
}

// ---------------- layernorm over 512 ----------------
__global__ void __launch_bounds__(128)
layernorm_kernel(const float* __restrict__ x, const float* __restrict__ g,
                 const float* __restrict__ bpar, float* __restrict__ out)
{
    int row = blockIdx.x;
    size_t o = (size_t)row * DMODEL;
    float v[4];
    float s = 0.f;
#pragma unroll
    for (int i = 0; i < 4; i++) {
        int c = threadIdx.x + i * 128;
        v[i] = x[o + c];
        s += v[i];
    }
    s = block_reduce_sum(s);
    float m = s * (1.f / (float)DMODEL);
    float ss = 0.f;
#pragma unroll
    for (int i = 0; i < 4; i++) { float d = v[i] - m; ss += d * d; }
    ss = block_reduce_sum(ss);
    float r = rsqrtf(ss * (1.f / (float)DMODEL) + 1e-5f);
#pragma unroll
    for (int i = 0; i < 4; i++) {
        int c = threadIdx.x + i * 128;
        out[o + c] = (v[i] - m) * r * g[c] + bpar[c];
    }
}

// ---------------- w1eff = w1[:, :512] + w1[:, 512:] ----------------
__global__ void __launch_bounds__(256)
w1eff_kernel(const float* __restrict__ w1, float* __restrict__ w1e)
{
    int idx = blockIdx.x * blockDim.x + threadIdx.x;
    if (idx >= 1024 * 512) return;
    int n = idx / 512, k = idx % 512;
    w1e[idx] = w1[n * 1024 + k] + w1[n * 1024 + 512 + k];
}

// ---------------- launch ----------------
extern "C" void kernel_launch(void* const* d_in, const int* in_sizes, int n_in,
                              void* d_out, int out_size)
{
    const float* x         = (const float*)d_in[0];
    const float* in_proj_w = (const float*)d_in[1];
    const float* conv_w    = (const float*)d_in[2];
    const float* conv_b    = (const float*)d_in[3];
    const float* dt_bias   = (const float*)d_in[4];
    const float* A_log     = (const float*)d_in[5];
    const float* Dv        = (const float*)d_in[6];
    const float* rms_w     = (const float*)d_in[7];
    const float* out_proj  = (const float*)d_in[8];
    const float* ln_g      = (const float*)d_in[9];
    const float* ln_b      = (const float*)d_in[10];
    const float* w1        = (const float*)d_in[11];
    const float* b1        = (const float*)d_in[12];
    const float* w2        = (const float*)d_in[13];
    const float* b2        = (const float*)d_in[14];
    float* outp            = (float*)d_out;

    float *p_zx, *p_xc, *p_ys, *p_yb, *p_y2, *p_yln, *p_h1, *p_w1e;
    cudaGetSymbolAddress((void**)&p_zx,  g_zx);
    cudaGetSymbolAddress((void**)&p_xc,  g_xc);
    cudaGetSymbolAddress((void**)&p_ys,  g_ys);
    cudaGetSymbolAddress((void**)&p_yb,  g_yb);
    cudaGetSymbolAddress((void**)&p_y2,  g_y2);
    cudaGetSymbolAddress((void**)&p_yln, g_yln);
    cudaGetSymbolAddress((void**)&p_h1,  g_h1);
    cudaGetSymbolAddress((void**)&p_w1e, g_w1e);

    static bool attr_done = false;
    if (!attr_done) {
        cudaFuncSetAttribute(hgemm3_kernel<0>, cudaFuncAttributeMaxDynamicSharedMemorySize, GSM_BYTES);
        cudaFuncSetAttribute(hgemm3_kernel<1>, cudaFuncAttributeMaxDynamicSharedMemorySize, GSM_BYTES);
        cudaFuncSetAttribute(hgemm3_kernel<2>, cudaFuncAttributeMaxDynamicSharedMemorySize, GSM_BYTES);
        attr_done = true;
    }

    w1eff_kernel<<<(1024 * 512 + 255) / 256, 256>>>(w1, p_w1e);

    // 1) in_proj
    {
        dim3 grid((NPROJ + 127) / 128, BL / 128);
        hgemm3_kernel<0><<<grid, 256, GSM_BYTES>>>(x, in_proj_w, nullptr, p_zx, BL, NPROJ, DMODEL);
    }
    // 2) conv + silu
    {
        size_t tot = (size_t)BL * CONVD;
        conv_silu_kernel<<<(unsigned)((tot + 255) / 256), 256>>>(p_zx, conv_w, conv_b, p_xc);
    }
    // 3) segmented selective scan
    scan_seg1_kernel<<<64 * SSEG, 256>>>(p_zx, p_xc, dt_bias, A_log, p_ys);
    scan_comb_kernel<<<64, 256>>>();
    scan_fix_kernel<<<64 * SSEG, 256>>>(p_xc, p_ys);
    // 4) gate + rmsnorm
    gate_rms_kernel<<<BL, 256>>>(p_ys, p_xc, p_zx, Dv, rms_w, p_yb);
    // 5) out_proj
    {
        dim3 grid(DMODEL / 128, BL / 128);
        hgemm3_kernel<0><<<grid, 256, GSM_BYTES>>>(p_yb, out_proj, nullptr, p_y2, BL, DMODEL, DINNER);
    }
    // 6) layernorm
    layernorm_kernel<<<BL, 128>>>(p_y2, ln_g, ln_b, p_yln);
    // 7) mlp hidden
    {
        dim3 grid(DINNER / 128, BL / 128);
        hgemm3_kernel<2><<<grid, 256, GSM_BYTES>>>(p_yln, p_w1e, b1, p_h1, BL, DINNER, DMODEL);
    }
    // 8) output
    {
        dim3 grid(DMODEL / 128, BL / 128);
        hgemm3_kernel<1><<<grid, 256, GSM_BYTES>>>(p_h1, w2, b2, outp, BL, DMODEL, DINNER);
    }
}

// round 7
// speedup vs baseline: 2.8914x; 1.0558x over previous
#include <cuda_runtime.h>
#include <cuda_bf16.h>
#include <math.h>
#include <stdint.h>

// ---------------- problem constants ----------------
#define BB      4
#define LL      4096
#define DMODEL  512
#define DINNER  1024
#define DSTATE  64
#define HEADD   64
#define NHEADS  16
#define CONVD   1152
#define NPROJ   2192
#define NPROJ_PAD 2304      // 18*128
#define BL      (BB*LL)

// scan segmentation
#define SSEG    16
#define SEGL    (LL / SSEG)   // 256

// ---------------- scratch ----------------
__device__ float g_zx [(size_t)BL * NPROJ];
__device__ float g_xc [(size_t)BL * CONVD];
__device__ float g_ys [(size_t)BL * DINNER];
__device__ float g_y2 [(size_t)BL * DMODEL];
__device__ float g_hseg[64 * SSEG * 4096];
__device__ float g_hst [64 * SSEG * 4096];
__device__ float g_cum [64 * LL];

// pre-split bf16 operands
__device__ __nv_bfloat16 g_xhi [(size_t)BL * DMODEL],  g_xlo [(size_t)BL * DMODEL];
__device__ __nv_bfloat16 g_winh[(size_t)NPROJ_PAD * DMODEL], g_winl[(size_t)NPROJ_PAD * DMODEL];
__device__ __nv_bfloat16 g_woh [DMODEL * DINNER], g_wol [DMODEL * DINNER];
__device__ __nv_bfloat16 g_w1h [DINNER * DMODEL], g_w1l [DINNER * DMODEL];
__device__ __nv_bfloat16 g_w2h [DMODEL * DINNER], g_w2l [DMODEL * DINNER];
__device__ __nv_bfloat16 g_ybh [(size_t)BL * DINNER], g_ybl [(size_t)BL * DINNER];
__device__ __nv_bfloat16 g_ylnh[(size_t)BL * DMODEL], g_ylnl[(size_t)BL * DMODEL];
__device__ __nv_bfloat16 g_h1h [(size_t)BL * DINNER], g_h1l [(size_t)BL * DINNER];

// ================= helpers =================
__device__ __forceinline__ unsigned pack_bf16(__nv_bfloat16 a, __nv_bfloat16 b) {
    unsigned short ua = *(unsigned short*)&a;
    unsigned short ub = *(unsigned short*)&b;
    return (unsigned)ua | ((unsigned)ub << 16);
}
__device__ __forceinline__ void ldsm_x4(unsigned &r0, unsigned &r1,
                                        unsigned &r2, unsigned &r3, unsigned addr) {
    asm volatile("ldmatrix.sync.aligned.m8n8.x4.shared.b16 {%0,%1,%2,%3}, [%4];"
                 : "=r"(r0), "=r"(r1), "=r"(r2), "=r"(r3) : "r"(addr));
}
__device__ __forceinline__ void mma16816(float* c, const unsigned* a, const unsigned* b) {
    asm volatile(
        "mma.sync.aligned.m16n8k16.row.col.f32.bf16.bf16.f32 "
        "{%0,%1,%2,%3}, {%4,%5,%6,%7}, {%8,%9}, {%0,%1,%2,%3};"
        : "+f"(c[0]), "+f"(c[1]), "+f"(c[2]), "+f"(c[3])
        : "r"(a[0]), "r"(a[1]), "r"(a[2]), "r"(a[3]), "r"(b[0]), "r"(b[1]));
}
__device__ __forceinline__ void cp16(unsigned dst, const void* src) {
    asm volatile("cp.async.cg.shared.global [%0], [%1], 16;" :: "r"(dst), "l"(src));
}

#define TILE_BYTES   16384
#define BUF_BYTES    (2 * TILE_BYTES)
#define GSM_BYTES    (2 * BUF_BYTES)

// ================= GEMM: C = A @ W^T, pre-split bf16 hi/lo operands ============
// EPI: 0 none, 1 +bias, 2 +bias+silu.  OSPLIT: 0 -> fp32 C, 1 -> bf16 hi/lo out.
template<int EPI, int OSPLIT>
__global__ void __launch_bounds__(256, 2)
hgemm3_kernel(const __nv_bfloat16* __restrict__ Ahi, const __nv_bfloat16* __restrict__ Alo,
              const __nv_bfloat16* __restrict__ Whi, const __nv_bfloat16* __restrict__ Wlo,
              const float* __restrict__ bias, float* __restrict__ C,
              __nv_bfloat16* __restrict__ Chi, __nv_bfloat16* __restrict__ Clo,
              int M, int N, int K)
{
    extern __shared__ char smem[];

    const int tid  = threadIdx.x;
    const int lane = tid & 31;
    const int wid  = tid >> 5;
    const int wm   = wid & 1;
    const int wn   = wid >> 1;
    const int m0   = blockIdx.y * 128;
    const int n0   = blockIdx.x * 128;

    // cp.async loader mapping: 256 threads = 128 rows x 2 k-halves
    const int lrow = tid >> 1;
    const int half = tid & 1;
    const int rsw  = lrow & 7;
    const int c0 = 2 * half, c1 = 2 * half + 1, c2 = 4 + 2 * half, c3 = 5 + 2 * half;

    const unsigned s_u32 = (unsigned)__cvta_generic_to_shared(&smem[0]);
    const unsigned abase = s_u32 + (unsigned)(lrow * 128);
    const unsigned bbase = s_u32 + (unsigned)(TILE_BYTES + lrow * 128);

    unsigned aBase[4]; int aSw[4];
    const int kcA = lane >> 4;
#pragma unroll
    for (int mi = 0; mi < 4; mi++) {
        int r = wm * 64 + mi * 16 + (lane & 7) + ((lane >> 3) & 1) * 8;
        aBase[mi] = s_u32 + (unsigned)(r * 128);
        aSw[mi] = r & 7;
    }
    unsigned bBase[2]; int bSw[2];
    const int kcB = (lane >> 3) & 1;
#pragma unroll
    for (int pj = 0; pj < 2; pj++) {
        int r = wn * 32 + pj * 16 + ((lane >> 4) & 1) * 8 + (lane & 7);
        bBase[pj] = s_u32 + (unsigned)(TILE_BYTES + r * 128);
        bSw[pj] = r & 7;
    }

    float acc[4][4][4];
#pragma unroll
    for (int i = 0; i < 4; i++)
#pragma unroll
        for (int j = 0; j < 4; j++)
#pragma unroll
            for (int q = 0; q < 4; q++) acc[i][j][q] = 0.f;

    auto issue = [&](int k0, int buf) {
        unsigned bo = (unsigned)(buf * BUF_BYTES);
        const __nv_bfloat16* sa  = Ahi + (size_t)(m0 + lrow) * K + k0 + half * 16;
        const __nv_bfloat16* sal = Alo + (size_t)(m0 + lrow) * K + k0 + half * 16;
        const __nv_bfloat16* sb  = Whi + (size_t)(n0 + lrow) * K + k0 + half * 16;
        const __nv_bfloat16* sbl = Wlo + (size_t)(n0 + lrow) * K + k0 + half * 16;
        cp16(abase + bo + (unsigned)((c0 ^ rsw) * 16), sa);
        cp16(abase + bo + (unsigned)((c1 ^ rsw) * 16), sa + 8);
        cp16(abase + bo + (unsigned)((c2 ^ rsw) * 16), sal);
        cp16(abase + bo + (unsigned)((c3 ^ rsw) * 16), sal + 8);
        cp16(bbase + bo + (unsigned)((c0 ^ rsw) * 16), sb);
        cp16(bbase + bo + (unsigned)((c1 ^ rsw) * 16), sb + 8);
        cp16(bbase + bo + (unsigned)((c2 ^ rsw) * 16), sbl);
        cp16(bbase + bo + (unsigned)((c3 ^ rsw) * 16), sbl + 8);
        asm volatile("cp.async.commit_group;" ::: "memory");
    };

    auto do_ks = [&](int ks, unsigned boff) {
        unsigned bh[4][2], bt[4][2];
#pragma unroll
        for (int pj = 0; pj < 2; pj++) {
            unsigned r0, r1, r2, r3;
            ldsm_x4(r0, r1, r2, r3,
                    bBase[pj] + boff + (unsigned)((((ks * 2 + kcB)) ^ bSw[pj]) * 16));
            bh[pj * 2][0] = r0; bh[pj * 2][1] = r1;
            bh[pj * 2 + 1][0] = r2; bh[pj * 2 + 1][1] = r3;
        }
#pragma unroll
        for (int pj = 0; pj < 2; pj++) {
            unsigned r0, r1, r2, r3;
            ldsm_x4(r0, r1, r2, r3,
                    bBase[pj] + boff + (unsigned)((((ks * 2 + kcB + 4)) ^ bSw[pj]) * 16));
            bt[pj * 2][0] = r0; bt[pj * 2][1] = r1;
            bt[pj * 2 + 1][0] = r2; bt[pj * 2 + 1][1] = r3;
        }
#pragma unroll
        for (int mi = 0; mi < 4; mi++) {
            unsigned a[4];
            ldsm_x4(a[0], a[1], a[2], a[3],
                    aBase[mi] + boff + (unsigned)((((ks * 2 + kcA)) ^ aSw[mi]) * 16));
#pragma unroll
            for (int nj = 0; nj < 4; nj++) mma16816(acc[mi][nj], a, bh[nj]);
#pragma unroll
            for (int nj = 0; nj < 4; nj++) mma16816(acc[mi][nj], a, bt[nj]);
            ldsm_x4(a[0], a[1], a[2], a[3],
                    aBase[mi] + boff + (unsigned)((((ks * 2 + kcA + 4)) ^ aSw[mi]) * 16));
#pragma unroll
            for (int nj = 0; nj < 4; nj++) mma16816(acc[mi][nj], a, bh[nj]);
        }
    };

    issue(0, 0);
    const int nk = K >> 5;
    for (int it = 0; it < nk; it++) {
        asm volatile("cp.async.wait_group 0;" ::: "memory");
        __syncthreads();
        if (it + 1 < nk) issue((it + 1) * 32, (it + 1) & 1);
        const unsigned boff = (unsigned)((it & 1) * BUF_BYTES);
        do_ks(0, boff);
        do_ks(1, boff);
    }

    // epilogue
    const int row0 = m0 + wm * 64 + (lane >> 2);
    const int col0 = n0 + wn * 32 + (lane & 3) * 2;
#pragma unroll
    for (int mi = 0; mi < 4; mi++) {
#pragma unroll
        for (int nj = 0; nj < 4; nj++) {
            int col = col0 + nj * 8;
            if (col < N) {
                float b0 = 0.f, b1 = 0.f;
                if (EPI >= 1) { b0 = bias[col]; b1 = bias[col + 1]; }
                float v0 = acc[mi][nj][0] + b0;
                float v1 = acc[mi][nj][1] + b1;
                float v2 = acc[mi][nj][2] + b0;
                float v3 = acc[mi][nj][3] + b1;
                if (EPI == 2) {
                    v0 = v0 / (1.f + expf(-v0));
                    v1 = v1 / (1.f + expf(-v1));
                    v2 = v2 / (1.f + expf(-v2));
                    v3 = v3 / (1.f + expf(-v3));
                }
                int r = row0 + mi * 16;
                if (OSPLIT) {
                    __nv_bfloat16 h0 = __float2bfloat16(v0), h1 = __float2bfloat16(v1);
                    __nv_bfloat16 h2 = __float2bfloat16(v2), h3 = __float2bfloat16(v3);
                    __nv_bfloat16 l0 = __float2bfloat16(v0 - __bfloat162float(h0));
                    __nv_bfloat16 l1 = __float2bfloat16(v1 - __bfloat162float(h1));
                    __nv_bfloat16 l2 = __float2bfloat16(v2 - __bfloat162float(h2));
                    __nv_bfloat16 l3 = __float2bfloat16(v3 - __bfloat162float(h3));
                    *(unsigned*)&Chi[(size_t)r * N + col]       = pack_bf16(h0, h1);
                    *(unsigned*)&Clo[(size_t)r * N + col]       = pack_bf16(l0, l1);
                    *(unsigned*)&Chi[(size_t)(r + 8) * N + col] = pack_bf16(h2, h3);
                    *(unsigned*)&Clo[(size_t)(r + 8) * N + col] = pack_bf16(l2, l3);
                } else {
                    float2 p0; p0.x = v0; p0.y = v1;
                    float2 p1; p1.x = v2; p1.y = v3;
                    *(float2*)&C[(size_t)r * N + col] = p0;
                    *(float2*)&C[(size_t)(r + 8) * N + col] = p1;
                }
            }
        }
    }
}

// ---------------- generic split: fp32 -> bf16 hi/lo (zero-pads tail) ----------------
__global__ void __launch_bounds__(256)
split_kernel(const float* __restrict__ src, __nv_bfloat16* __restrict__ hi,
             __nv_bfloat16* __restrict__ lo, int n, int total)
{
    int idx = blockIdx.x * blockDim.x + threadIdx.x;
    if (idx >= total) return;
    float v = (idx < n) ? src[idx] : 0.f;
    __nv_bfloat16 h = __float2bfloat16(v);
    hi[idx] = h;
    lo[idx] = __float2bfloat16(v - __bfloat162float(h));
}

// ---------------- w1eff = w1[:, :512] + w1[:, 512:], split ----------------
__global__ void __launch_bounds__(256)
w1eff_split_kernel(const float* __restrict__ w1, __nv_bfloat16* __restrict__ hi,
                   __nv_bfloat16* __restrict__ lo)
{
    int idx = blockIdx.x * blockDim.x + threadIdx.x;
    if (idx >= 1024 * 512) return;
    int n = idx / 512, k = idx % 512;
    float v = w1[n * 1024 + k] + w1[n * 1024 + 512 + k];
    __nv_bfloat16 h = __float2bfloat16(v);
    hi[idx] = h;
    lo[idx] = __float2bfloat16(v - __bfloat162float(h));
}

// ---------------- conv (anti-causal) + silu ----------------
__global__ void __launch_bounds__(256)
conv_silu_kernel(const float* __restrict__ zx, const float* __restrict__ cw,
                 const float* __restrict__ cb, float* __restrict__ xc)
{
    size_t idx = (size_t)blockIdx.x * blockDim.x + threadIdx.x;
    if (idx >= (size_t)BL * CONVD) return;
    int c  = (int)(idx % CONVD);
    int bl = (int)(idx / CONVD);
    int l  = bl % LL;

    float acc = cb[c];
    const float* base = zx + (size_t)bl * NPROJ + DINNER + c;
#pragma unroll
    for (int k = 0; k < 4; k++) {
        int off = 3 - k;
        if (l + off < LL) acc += cw[c * 4 + k] * base[(size_t)off * NPROJ];
    }
    acc = acc / (1.f + expf(-acc));
    xc[idx] = acc;
}

// ---------------- scan pass 1 ----------------
__global__ void __launch_bounds__(256)
scan_seg1_kernel(const float* __restrict__ zx, const float* __restrict__ xc,
                 const float* __restrict__ dt_bias, const float* __restrict__ A_log,
                 float* __restrict__ yout)
{
    int blk = blockIdx.x;
    int seg = blk & (SSEG - 1);
    int bh  = blk / SSEG;
    int b = bh >> 4, h = bh & 15;
    int tid = threadIdx.x;
    int pl = tid >> 2;
    int ng = tid & 3;

    float Acoef = -expf(A_log[h]);
    float dtb   = dt_bias[h];

    __shared__ float sB[2][8][64], sC[2][8][64], sX[2][8][64];
    __shared__ float sdt[2][8], sDA[2][8];

    float hs[16];
#pragma unroll
    for (int j = 0; j < 16; j++) hs[j] = 0.f;

    float rBC[4], rX[2], rDR = 0.f;
    const int sBeg = seg * SEGL;
    const int sEnd = sBeg + SEGL;

    float runP = 1.f;

    auto preload = [&](int s0) {
#pragma unroll
        for (int i = 0; i < 4; i++) {
            int e = tid + i * 256;
            int t = e >> 7, q = e & 127;
            int bl = b * LL + (LL - 1 - (s0 + t));
            rBC[i] = xc[(size_t)bl * CONVD + DINNER + q];
        }
#pragma unroll
        for (int i = 0; i < 2; i++) {
            int e = tid + i * 256;
            int t = e >> 6, j = e & 63;
            int bl = b * LL + (LL - 1 - (s0 + t));
            rX[i] = xc[(size_t)bl * CONVD + h * HEADD + j];
        }
        if (tid < 8) {
            int bl = b * LL + (LL - 1 - (s0 + tid));
            rDR = zx[(size_t)bl * NPROJ + (2 * DINNER + 2 * DSTATE) + h];
        }
    };
    auto commit_smem = [&](int buf) {
#pragma unroll
        for (int i = 0; i < 4; i++) {
            int e = tid + i * 256;
            int t = e >> 7, q = e & 127;
            if (q < 64) sB[buf][t][q] = rBC[i]; else sC[buf][t][q - 64] = rBC[i];
        }
#pragma unroll
        for (int i = 0; i < 2; i++) {
            int e = tid + i * 256;
            int t = e >> 6, j = e & 63;
            sX[buf][t][j] = rX[i];
        }
        if (tid < 8) {
            float dr = rDR + dtb;
            float dt = (dr > 20.f) ? dr : log1pf(expf(dr));
            sdt[buf][tid] = dt;
            sDA[buf][tid] = expf(dt * Acoef);
        }
    };

    preload(sBeg);
    commit_smem(0);
    __syncthreads();

    for (int s0 = sBeg; s0 < sEnd; s0 += 8) {
        int buf = ((s0 - sBeg) >> 3) & 1;
        bool more = (s0 + 8) < sEnd;
        if (more) preload(s0 + 8);

        if (tid == 0) {
            float* cw = &g_cum[(size_t)bh * LL + s0];
#pragma unroll
            for (int t = 0; t < 8; t++) { runP *= sDA[buf][t]; cw[t] = runP; }
        }

        float yv[8];
#pragma unroll
        for (int t = 0; t < 8; t++) {
            float dA  = sDA[buf][t];
            float dtx = sdt[buf][t] * sX[buf][t][pl];
            float yp = 0.f;
#pragma unroll
            for (int u = 0; u < 4; u++) {
                float4 bb = *(const float4*)&sB[buf][t][u * 16 + ng * 4];
                hs[u*4+0] = hs[u*4+0] * dA + dtx * bb.x;
                hs[u*4+1] = hs[u*4+1] * dA + dtx * bb.y;
                hs[u*4+2] = hs[u*4+2] * dA + dtx * bb.z;
                hs[u*4+3] = hs[u*4+3] * dA + dtx * bb.w;
            }
#pragma unroll
            for (int u = 0; u < 4; u++) {
                float4 cc = *(const float4*)&sC[buf][t][u * 16 + ng * 4];
                yp += hs[u*4+0] * cc.x + hs[u*4+1] * cc.y
                    + hs[u*4+2] * cc.z + hs[u*4+3] * cc.w;
            }
            yv[t] = yp;
        }
#pragma unroll
        for (int t = 0; t < 8; t++) yv[t] += __shfl_xor_sync(0xffffffffu, yv[t], 1);
#pragma unroll
        for (int t = 0; t < 8; t++) yv[t] += __shfl_xor_sync(0xffffffffu, yv[t], 2);
        if (ng == 0) {
#pragma unroll
            for (int t = 0; t < 8; t++) {
                int l = LL - 1 - (s0 + t);
                yout[((size_t)(b * LL + l)) * DINNER + h * HEADD + pl] = yv[t];
            }
        }

        if (more) commit_smem(buf ^ 1);
        __syncthreads();
    }

    {
        float* hd = &g_hseg[((size_t)blk) * 4096 + pl * 64];
#pragma unroll
        for (int j = 0; j < 16; j++) {
            int n = ((j >> 2) << 4) + (ng << 2) + (j & 3);
            hd[n] = hs[j];
        }
    }
}

// ---------------- scan pass 2 ----------------
__global__ void __launch_bounds__(256)
scan_comb_kernel()
{
    int bh = blockIdx.x;
    int tid = threadIdx.x;
    float hst[16];
#pragma unroll
    for (int i = 0; i < 16; i++) hst[i] = 0.f;

    for (int seg = 0; seg < SSEG; seg++) {
        float P = g_cum[(size_t)bh * LL + seg * SEGL + SEGL - 1];
#pragma unroll
        for (int i = 0; i < 16; i++) {
            int e = tid + i * 256;
            size_t base = ((size_t)(bh * SSEG + seg)) * 4096 + e;
            g_hst[base] = hst[i];
            hst[i] = P * hst[i] + g_hseg[base];
        }
    }
}

// ---------------- scan pass 3 ----------------
__global__ void __launch_bounds__(256)
scan_fix_kernel(const float* __restrict__ xc, float* __restrict__ yout)
{
    int blk = blockIdx.x;
    int seg = blk & (SSEG - 1);
    if (seg == 0) return;
    int bh  = blk / SSEG;
    int b = bh >> 4, h = bh & 15;
    int tid = threadIdx.x;
    int pl = tid >> 2;
    int ng = tid & 3;

    float hs[16];
    {
        const float* hp = &g_hst[((size_t)blk) * 4096 + pl * 64];
#pragma unroll
        for (int j = 0; j < 16; j++) {
            int n = ((j >> 2) << 4) + (ng << 2) + (j & 3);
            hs[j] = hp[n];
        }
    }

    __shared__ float sC[8][64];
    __shared__ float sCum[8];
    const int sBeg = seg * SEGL;

    for (int s0 = sBeg; s0 < sBeg + SEGL; s0 += 8) {
#pragma unroll
        for (int i = 0; i < 2; i++) {
            int e = tid + i * 256;
            int t = e >> 6, q = e & 63;
            int bl = b * LL + (LL - 1 - (s0 + t));
            sC[t][q] = xc[(size_t)bl * CONVD + DINNER + DSTATE + q];
        }
        if (tid < 8) sCum[tid] = g_cum[(size_t)bh * LL + s0 + tid];
        __syncthreads();

        float yv[8];
#pragma unroll
        for (int t = 0; t < 8; t++) {
            float yp = 0.f;
#pragma unroll
            for (int u = 0; u < 4; u++) {
                float4 cc = *(const float4*)&sC[t][u * 16 + ng * 4];
                yp += hs[u*4+0] * cc.x + hs[u*4+1] * cc.y
                    + hs[u*4+2] * cc.z + hs[u*4+3] * cc.w;
            }
            yv[t] = yp * sCum[t];
        }
#pragma unroll
        for (int t = 0; t < 8; t++) yv[t] += __shfl_xor_sync(0xffffffffu, yv[t], 1);
#pragma unroll
        for (int t = 0; t < 8; t++) yv[t] += __shfl_xor_sync(0xffffffffu, yv[t], 2);
        if (ng == 0) {
#pragma unroll
            for (int t = 0; t < 8; t++) {
                int l = LL - 1 - (s0 + t);
                size_t idx = ((size_t)(b * LL + l)) * DINNER + h * HEADD + pl;
                yout[idx] += yv[t];
            }
        }
        __syncthreads();
    }
}

// ---------------- block reduction helper ----------------
__device__ __forceinline__ float block_reduce_sum(float v) {
    __shared__ float sred[32];
    int lane = threadIdx.x & 31, w = threadIdx.x >> 5;
#pragma unroll
    for (int o = 16; o; o >>= 1) v += __shfl_xor_sync(0xffffffffu, v, o);
    if (lane == 0) sred[w] = v;
    __syncthreads();
    int nw = blockDim.x >> 5;
    float r = (threadIdx.x < nw) ? sred[threadIdx.x] : 0.f;
    if (w == 0) {
#pragma unroll
        for (int o = 16; o; o >>= 1) r += __shfl_xor_sync(0xffffffffu, r, o);
        if (lane == 0) sred[0] = r;
    }
    __syncthreads();
    float out = sred[0];
    __syncthreads();
    return out;
}

// ---------------- gate + rmsnorm -> split bf16 ----------------
__global__ void __launch_bounds__(256)
gate_rms_kernel(const float* __restrict__ ys, const float* __restrict__ xc,
                const float* __restrict__ zx, const float* __restrict__ Dv,
                const float* __restrict__ rw,
                __nv_bfloat16* __restrict__ ybh, __nv_bfloat16* __restrict__ ybl)
{
    int row = blockIdx.x;
    size_t oy = (size_t)row * DINNER, oc = (size_t)row * CONVD, oz = (size_t)row * NPROJ;
    float v[4];
    float ss = 0.f;
#pragma unroll
    for (int i = 0; i < 4; i++) {
        int c = threadIdx.x + i * 256;
        float z = zx[oz + c];
        float sz = z / (1.f + expf(-z));
        float val = (ys[oy + c] + Dv[c >> 6] * xc[oc + c]) * sz;
        v[i] = val;
        ss += val * val;
    }
    ss = block_reduce_sum(ss);
    float r = rsqrtf(ss * (1.f / (float)DINNER) + 1e-5f);
#pragma unroll
    for (int i = 0; i < 4; i++) {
        int c = threadIdx.x + i * 256;
        float val = v[i] * r * rw[c];
        __nv_bfloat16 hh = __float2bfloat16(val);
        ybh[oy + c] = hh;
        ybl[oy + c] = __float2bfloat16(val - __bfloat162float(hh));
    }
}

// ---------------- layernorm -> split bf16 ----------------
__global__ void __launch_bounds__(128)
layernorm_kernel(const float* __restrict__ x, const float* __restrict__ g,
                 const float* __restrict__ bpar,
                 __nv_bfloat16* __restrict__ oh, __nv_bfloat16* __restrict__ ol)
{
    int row = blockIdx.x;
    size_t o = (size_t)row * DMODEL;
    float v[4];
    float s = 0.f;
#pragma unroll
    for (int i = 0; i < 4; i++) {
        int c = threadIdx.x + i * 128;
        v[i] = x[o + c];
        s += v[i];
    }
    s = block_reduce_sum(s);
    float m = s * (1.f / (float)DMODEL);
    float ss = 0.f;
#pragma unroll
    for (int i = 0; i < 4; i++) { float d = v[i] - m; ss += d * d; }
    ss = block_reduce_sum(ss);
    float r = rsqrtf(ss * (1.f / (float)DMODEL) + 1e-5f);
#pragma unroll
    for (int i = 0; i < 4; i++) {
        int c = threadIdx.x + i * 128;
        float val = (v[i] - m) * r * g[c] + bpar[c];
        __nv_bfloat16 hh = __float2bfloat16(val);
        oh[o + c] = hh;
        ol[o + c] = __float2bfloat16(val - __bfloat162float(hh));
    }
}

// ---------------- launch ----------------
extern "C" void kernel_launch(void* const* d_in, const int* in_sizes, int n_in,
                              void* d_out, int out_size)
{
    const float* x         = (const float*)d_in[0];
    const float* in_proj_w = (const float*)d_in[1];
    const float* conv_w    = (const float*)d_in[2];
    const float* conv_b    = (const float*)d_in[3];
    const float* dt_bias   = (const float*)d_in[4];
    const float* A_log     = (const float*)d_in[5];
    const float* Dv        = (const float*)d_in[6];
    const float* rms_w     = (const float*)d_in[7];
    const float* out_proj  = (const float*)d_in[8];
    const float* ln_g      = (const float*)d_in[9];
    const float* ln_b      = (const float*)d_in[10];
    const float* w1        = (const float*)d_in[11];
    const float* b1        = (const float*)d_in[12];
    const float* w2        = (const float*)d_in[13];
    const float* b2        = (const float*)d_in[14];
    float* outp            = (float*)d_out;

    float *p_zx, *p_xc, *p_ys, *p_y2;
    cudaGetSymbolAddress((void**)&p_zx,  g_zx);
    cudaGetSymbolAddress((void**)&p_xc,  g_xc);
    cudaGetSymbolAddress((void**)&p_ys,  g_ys);
    cudaGetSymbolAddress((void**)&p_y2,  g_y2);

    __nv_bfloat16 *p_xhi, *p_xlo, *p_winh, *p_winl, *p_woh, *p_wol;
    __nv_bfloat16 *p_w1h, *p_w1l, *p_w2h, *p_w2l;
    __nv_bfloat16 *p_ybh, *p_ybl, *p_ylnh, *p_ylnl, *p_h1h, *p_h1l;
    cudaGetSymbolAddress((void**)&p_xhi,  g_xhi);
    cudaGetSymbolAddress((void**)&p_xlo,  g_xlo);
    cudaGetSymbolAddress((void**)&p_winh, g_winh);
    cudaGetSymbolAddress((void**)&p_winl, g_winl);
    cudaGetSymbolAddress((void**)&p_woh,  g_woh);
    cudaGetSymbolAddress((void**)&p_wol,  g_wol);
    cudaGetSymbolAddress((void**)&p_w1h,  g_w1h);
    cudaGetSymbolAddress((void**)&p_w1l,  g_w1l);
    cudaGetSymbolAddress((void**)&p_w2h,  g_w2h);
    cudaGetSymbolAddress((void**)&p_w2l,  g_w2l);
    cudaGetSymbolAddress((void**)&p_ybh,  g_ybh);
    cudaGetSymbolAddress((void**)&p_ybl,  g_ybl);
    cudaGetSymbolAddress((void**)&p_ylnh, g_ylnh);
    cudaGetSymbolAddress((void**)&p_ylnl, g_ylnl);
    cudaGetSymbolAddress((void**)&p_h1h,  g_h1h);
    cudaGetSymbolAddress((void**)&p_h1l,  g_h1l);

    static bool attr_done = false;
    if (!attr_done) {
        cudaFuncSetAttribute(hgemm3_kernel<0,0>, cudaFuncAttributeMaxDynamicSharedMemorySize, GSM_BYTES);
        cudaFuncSetAttribute(hgemm3_kernel<1,0>, cudaFuncAttributeMaxDynamicSharedMemorySize, GSM_BYTES);
        cudaFuncSetAttribute(hgemm3_kernel<2,1>, cudaFuncAttributeMaxDynamicSharedMemorySize, GSM_BYTES);
        attr_done = true;
    }

    // operand splitting (weights + x)
    {
        int n, tot;
        n = tot = BL * DMODEL;
        split_kernel<<<(tot + 255) / 256, 256>>>(x, p_xhi, p_xlo, n, tot);
        n = NPROJ * DMODEL; tot = NPROJ_PAD * DMODEL;
        split_kernel<<<(tot + 255) / 256, 256>>>(in_proj_w, p_winh, p_winl, n, tot);
        n = tot = DMODEL * DINNER;
        split_kernel<<<(tot + 255) / 256, 256>>>(out_proj, p_woh, p_wol, n, tot);
        split_kernel<<<(tot + 255) / 256, 256>>>(w2, p_w2h, p_w2l, n, tot);
        w1eff_split_kernel<<<(1024 * 512 + 255) / 256, 256>>>(w1, p_w1h, p_w1l);
    }

    // 1) in_proj
    {
        dim3 grid(NPROJ_PAD / 128, BL / 128);
        hgemm3_kernel<0,0><<<grid, 256, GSM_BYTES>>>(p_xhi, p_xlo, p_winh, p_winl,
                                                     nullptr, p_zx, nullptr, nullptr,
                                                     BL, NPROJ, DMODEL);
    }
    // 2) conv + silu
    {
        size_t tot = (size_t)BL * CONVD;
        conv_silu_kernel<<<(unsigned)((tot + 255) / 256), 256>>>(p_zx, conv_w, conv_b, p_xc);
    }
    // 3) segmented selective scan
    scan_seg1_kernel<<<64 * SSEG, 256>>>(p_zx, p_xc, dt_bias, A_log, p_ys);
    scan_comb_kernel<<<64, 256>>>();
    scan_fix_kernel<<<64 * SSEG, 256>>>(p_xc, p_ys);
    // 4) gate + rmsnorm -> split
    gate_rms_kernel<<<BL, 256>>>(p_ys, p_xc, p_zx, Dv, rms_w, p_ybh, p_ybl);
    // 5) out_proj
    {
        dim3 grid(DMODEL / 128, BL / 128);
        hgemm3_kernel<0,0><<<grid, 256, GSM_BYTES>>>(p_ybh, p_ybl, p_woh, p_wol,
                                                     nullptr, p_y2, nullptr, nullptr,
                                                     BL, DMODEL, DINNER);
    }
    // 6) layernorm -> split
    layernorm_kernel<<<BL, 128>>>(p_y2, ln_g, ln_b, p_ylnh, p_ylnl);
    // 7) mlp hidden (bias + silu, split out)
    {
        dim3 grid(DINNER / 128, BL / 128);
        hgemm3_kernel<2,1><<<grid, 256, GSM_BYTES>>>(p_ylnh, p_ylnl, p_w1h, p_w1l,
                                                     b1, nullptr, p_h1h, p_h1l,
                                                     BL, DINNER, DMODEL);
    }
    // 8) output (bias)
    {
        dim3 grid(DMODEL / 128, BL / 128);
        hgemm3_kernel<1,0><<<grid, 256, GSM_BYTES>>>(p_h1h, p_h1l, p_w2h, p_w2l,
                                                     b2, outp, nullptr, nullptr,
                                                     BL, DMODEL, DINNER);
    }
}